// round 3
// baseline (speedup 1.0000x reference)
#include <cuda_runtime.h>
#include <math.h>

#define BB 8
#define DD 64
#define HH 128
#define WW 256

// Scratch (static device globals — no runtime allocation).
// g_xh  : horizontal input,  layout [w][h*B+b][d]           = [256][1024][64]
// g_vbuf: horizontal output / vertical input, [h][w*B+b][c] = [128][2048][128]
// g_vout: vertical output, [h][w*B+b][c]                    = [128][2048][128]
__device__ float g_xh[(size_t)WW * HH * BB * DD];
__device__ float g_vbuf[(size_t)HH * WW * BB * 128];
__device__ float g_vout[(size_t)HH * WW * BB * 128];

__device__ __forceinline__ float sigm(float x) {
    return 1.0f / (1.0f + __expf(-x));
}
__device__ __forceinline__ float tanh_fast(float x) {
    x = fminf(15.0f, fmaxf(-15.0f, x));
    float e = __expf(2.0f * x);
    return (e - 1.0f) / (e + 1.0f);
}

// Packed dual-FMA: d.lo += a.lo*b.lo ; d.hi += a.hi*b.hi   (SASS FFMA2)
__device__ __forceinline__ void ffma2(unsigned long long& acc,
                                      unsigned long long a,
                                      unsigned long long b) {
    asm("fma.rn.f32x2 %0, %1, %2, %0;" : "+l"(acc) : "l"(a), "l"(b));
}

union F2U {
    unsigned long long u;
    float2 f;
};

// img[b][d][h][w]  ->  g_xh[w][h*8+b][d]
__global__ void transpose_in_k(const float* __restrict__ img) {
    __shared__ float tile[32][33];
    const int tx = threadIdx.x, ty = threadIdx.y;
    const int b = blockIdx.z & 7, h = blockIdx.z >> 3;
    const int w0 = blockIdx.x * 32, d0 = blockIdx.y * 32;
#pragma unroll
    for (int i = 0; i < 32; i += 8) {
        int d = d0 + ty + i;
        tile[ty + i][tx] = img[(((size_t)b * DD + d) * HH + h) * WW + w0 + tx];
    }
    __syncthreads();
#pragma unroll
    for (int i = 0; i < 32; i += 8) {
        int w = w0 + ty + i;
        g_xh[((size_t)w * (HH * BB) + blockIdx.z) * DD + d0 + tx] = tile[tx][ty + i];
    }
}

// g_vout[h][w*8+b][c]  ->  out[b][c][h][w]
__global__ void transpose_out_k(float* __restrict__ out) {
    __shared__ float tile[32][33];
    const int tx = threadIdx.x, ty = threadIdx.y;
    const int b = blockIdx.z & 7, h = blockIdx.z >> 3;
    const int w0 = blockIdx.x * 32, c0 = blockIdx.y * 32;
#pragma unroll
    for (int i = 0; i < 32; i += 8) {
        int w = w0 + ty + i;
        tile[ty + i][tx] =
            g_vout[(size_t)h * (WW * BB * 128) + ((size_t)w * BB + b) * 128 + c0 + tx];
    }
    __syncthreads();
#pragma unroll
    for (int i = 0; i < 32; i += 8) {
        int c = c0 + ty + i;
        out[(((size_t)b * 128 + c) * HH + h) * WW + w0 + tx] = tile[tx][ty + i];
    }
}

// Persistent-state bidirectional LSTM pass with packed FFMA2 math.
//  VERT=false: x = g_xh  [T=256][1024][64],  out = g_vbuf
//  VERT=true : x = g_vbuf[T=128][2048][128], out = g_vout
// One CTA = one direction x NSEQ sequences. Weights [Wih|Whh] (256 x KD fp32)
// + hidden state live in shared; cell state in registers.
// Thread tile: 8 sequences x 1 j x 4 gates -> 32 packed-f32x2 accumulators.
// Threads: (NSEQ/8) seq-groups * 64 j = NSEQ*8.
template <bool VERT, int T, int STOT, int IN, int NSEQ, int OT, int SDIV, int OHI>
__global__ void __launch_bounds__(256, 1)
lstm_pass(const float* __restrict__ WihF, const float* __restrict__ WhhF,
          const float* __restrict__ bihF, const float* __restrict__ bhhF,
          const float* __restrict__ WihB, const float* __restrict__ WhhB,
          const float* __restrict__ bihB, const float* __restrict__ bhhB) {
    constexpr int KD = IN + 64;
    constexpr int KDP = KD + 4;   // row pad -> lane stride 4 banks, conflict-free LDS.128
    constexpr int NT = NSEQ * 8;
    constexpr int LPT = (NSEQ * IN) / (4 * NT);  // float4 x-loads per thread per step

    const float* x = VERT ? g_vbuf : g_xh;
    float* outbuf = VERT ? g_vout : g_vbuf;

    extern __shared__ float sm[];
    float* Wsh = sm;                        // 256 * KDP
    float* insh = sm + 256 * KDP;           // NSEQ * KDP   ([x_t | h_t] per sequence)
    float* bsum = insh + NSEQ * KDP;        // 256

    const int tid = threadIdx.x;
    const int dir = blockIdx.y;
    const int s0 = blockIdx.x * NSEQ;

    const float* Wih = dir ? WihB : WihF;
    const float* Whh = dir ? WhhB : WhhF;
    const float* bih = dir ? bihB : bihF;
    const float* bhh = dir ? bhhB : bhhF;

    for (int i = tid; i < 256 * IN; i += NT)
        Wsh[(i / IN) * KDP + (i % IN)] = Wih[i];
    for (int i = tid; i < 256 * 64; i += NT)
        Wsh[(i / 64) * KDP + IN + (i % 64)] = Whh[i];
    for (int i = tid; i < 256; i += NT)
        bsum[i] = bih[i] + bhh[i];
    for (int i = tid; i < NSEQ * 64; i += NT)
        insh[(i / 64) * KDP + IN + (i % 64)] = 0.0f;    // h_0 = 0

    // load x at first timestep
    {
        int tt0 = dir ? (T - 1) : 0;
        const float4* src = (const float4*)(x + ((size_t)tt0 * STOT + s0) * IN);
#pragma unroll
        for (int i = 0; i < LPT; i++) {
            int p4 = tid + i * NT;
            float4 v = src[p4];
            int p = p4 * 4;
            *(float4*)&insh[(p / IN) * KDP + (p % IN)] = v;
        }
    }
    __syncthreads();

    const int jgrp = tid & 63;   // j in [0,64)
    const int sgrp = tid >> 6;   // sequence group (8 seqs each)

    float bj[4];
#pragma unroll
    for (int g = 0; g < 4; g++) bj[g] = bsum[g * 64 + jgrp];

    unsigned long long acc[8][4];   // packed f32x2 partial sums [ss][gate]
    float creg[8];
#pragma unroll
    for (int ss = 0; ss < 8; ss++) {
        creg[ss] = 0.0f;
#pragma unroll
        for (int g = 0; g < 4; g++) {
            F2U z; z.f = make_float2(bj[g], 0.0f);
            acc[ss][g] = z.u;
        }
    }

    const float* wbase = &Wsh[jgrp * KDP];        // gate g row at + g*64*KDP
    const float* ibase = &insh[sgrp * 8 * KDP];   // seq ss row at + ss*KDP

    for (int t = 0; t < T; t++) {
        const int tt = dir ? (T - 1 - t) : t;
        float4 pre[LPT];
        const bool havepre = (t + 1 < T);
        if (havepre) {
            int tn = dir ? (tt - 1) : (tt + 1);
            const float4* src = (const float4*)(x + ((size_t)tn * STOT + s0) * IN);
#pragma unroll
            for (int i = 0; i < LPT; i++) pre[i] = src[tid + i * NT];
        }

        // gates = [x_t | h_t] @ [Wih | Whh]^T  (bias pre-loaded into acc.lo)
#pragma unroll 4
        for (int k = 0; k < KD; k += 4) {
            ulonglong2 w0 = *(const ulonglong2*)(wbase + 0 * 64 * KDP + k);
            ulonglong2 w1 = *(const ulonglong2*)(wbase + 1 * 64 * KDP + k);
            ulonglong2 w2 = *(const ulonglong2*)(wbase + 2 * 64 * KDP + k);
            ulonglong2 w3 = *(const ulonglong2*)(wbase + 3 * 64 * KDP + k);
#pragma unroll
            for (int ss = 0; ss < 8; ss++) {
                ulonglong2 xv = *(const ulonglong2*)(ibase + ss * KDP + k);
                ffma2(acc[ss][0], xv.x, w0.x);
                ffma2(acc[ss][1], xv.x, w1.x);
                ffma2(acc[ss][2], xv.x, w2.x);
                ffma2(acc[ss][3], xv.x, w3.x);
                ffma2(acc[ss][0], xv.y, w0.y);
                ffma2(acc[ss][1], xv.y, w1.y);
                ffma2(acc[ss][2], xv.y, w2.y);
                ffma2(acc[ss][3], xv.y, w3.y);
            }
        }
        __syncthreads();   // all reads of insh done

#pragma unroll
        for (int ss = 0; ss < 8; ss++) {
            int ls = sgrp * 8 + ss;
            int s = s0 + ls;
            F2U a0, a1, a2, a3;
            a0.u = acc[ss][0]; a1.u = acc[ss][1];
            a2.u = acc[ss][2]; a3.u = acc[ss][3];
            float iv = sigm(a0.f.x + a0.f.y);
            float fv = sigm(a1.f.x + a1.f.y);
            float gv = tanh_fast(a2.f.x + a2.f.y);
            float ov = sigm(a3.f.x + a3.f.y);
            float c = fv * creg[ss] + iv * gv;
            creg[ss] = c;
            float hv = ov * tanh_fast(c);
            insh[ls * KDP + IN + jgrp] = hv;
            size_t oidx = (size_t)(s / SDIV) * OHI + (size_t)(s % SDIV) * 128 +
                          (size_t)tt * OT + (size_t)dir * 64 + jgrp;
            outbuf[oidx] = hv;
#pragma unroll
            for (int g = 0; g < 4; g++) {
                F2U z; z.f = make_float2(bj[g], 0.0f);
                acc[ss][g] = z.u;
            }
        }
        if (havepre) {
#pragma unroll
            for (int i = 0; i < LPT; i++) {
                int p = (tid + i * NT) * 4;
                *(float4*)&insh[(p / IN) * KDP + (p % IN)] = pre[i];
            }
        }
        __syncthreads();   // new x_t+1 / h_t+1 visible
    }
}

extern "C" void kernel_launch(void* const* d_in, const int* in_sizes, int n_in,
                              void* d_out, int out_size) {
    const float* img    = (const float*)d_in[0];
    const float* hWihF  = (const float*)d_in[1];
    const float* hWhhF  = (const float*)d_in[2];
    const float* hbihF  = (const float*)d_in[3];
    const float* hbhhF  = (const float*)d_in[4];
    const float* hWihB  = (const float*)d_in[5];
    const float* hWhhB  = (const float*)d_in[6];
    const float* hbihB  = (const float*)d_in[7];
    const float* hbhhB  = (const float*)d_in[8];
    const float* vWihF  = (const float*)d_in[9];
    const float* vWhhF  = (const float*)d_in[10];
    const float* vbihF  = (const float*)d_in[11];
    const float* vbhhF  = (const float*)d_in[12];
    const float* vWihB  = (const float*)d_in[13];
    const float* vWhhB  = (const float*)d_in[14];
    const float* vbihB  = (const float*)d_in[15];
    const float* vbhhB  = (const float*)d_in[16];
    float* out = (float*)d_out;

    auto hK = lstm_pass<false, 256, 1024, 64, 16, 1024, 8, 262144>;
    auto vK = lstm_pass<true, 128, 2048, 128, 32, 262144, (1 << 28), 0>;

    const int smemH = (256 * (64 + 64 + 4) + 16 * (64 + 64 + 4) + 256) * 4;   // 144,640 B
    const int smemV = (256 * (128 + 64 + 4) + 32 * (128 + 64 + 4) + 256) * 4; // 226,816 B
    cudaFuncSetAttribute(hK, cudaFuncAttributeMaxDynamicSharedMemorySize, smemH);
    cudaFuncSetAttribute(vK, cudaFuncAttributeMaxDynamicSharedMemorySize, smemV);

    // 1) img -> g_xh  (coalesced transpose)
    transpose_in_k<<<dim3(WW / 32, DD / 32, HH * BB), dim3(32, 8)>>>(img);

    // 2) horizontal biLSTM: g_xh -> g_vbuf   (128 threads, 128 CTAs)
    hK<<<dim3(1024 / 16, 2), 128, smemH>>>(hWihF, hWhhF, hbihF, hbhhF,
                                           hWihB, hWhhB, hbihB, hbhhB);

    // 3) vertical biLSTM: g_vbuf -> g_vout   (256 threads, 128 CTAs)
    vK<<<dim3(2048 / 32, 2), 256, smemV>>>(vWihF, vWhhF, vbihF, vbhhF,
                                           vWihB, vWhhB, vbihB, vbhhB);

    // 4) g_vout -> out  (coalesced transpose)
    transpose_out_k<<<dim3(WW / 32, 128 / 32, HH * BB), dim3(32, 8)>>>(out);
}

// round 8
// speedup vs baseline: 1.3425x; 1.3425x over previous
#include <cuda_runtime.h>
#include <cuda_bf16.h>
#include <math.h>
#include <stdint.h>

#define BB 8
#define DD 64
#define HH 128
#define WW 256

// ---------------- scratch (static device globals) ----------------
// NOTE: these must ONLY be referenced from device code (host-side symbol use
// yields the host shadow address — silently wrong under ATS on GB300).
__device__ float g_xh[(size_t)WW * HH * BB * DD];       // [w][h*8+b][64]
__device__ float g_vbuf[(size_t)HH * WW * BB * 128];    // [h][w*8+b][128]
__device__ float g_vout[(size_t)HH * WW * BB * 128];    // [h][w*8+b][128]
__device__ float g_gx[(size_t)2 * 262144 * 256];        // [dir][token][256]

__device__ __forceinline__ void mma_bf16(float* c, const uint32_t* a, const uint32_t* b) {
    asm volatile(
        "mma.sync.aligned.m16n8k16.row.col.f32.bf16.bf16.f32 "
        "{%0,%1,%2,%3}, {%4,%5,%6,%7}, {%8,%9}, {%0,%1,%2,%3};"
        : "+f"(c[0]), "+f"(c[1]), "+f"(c[2]), "+f"(c[3])
        : "r"(a[0]), "r"(a[1]), "r"(a[2]), "r"(a[3]), "r"(b[0]), "r"(b[1]));
}

__device__ __forceinline__ uint32_t pack_bf16x2(float a, float b) {
    uint32_t r;
    asm("{ .reg .b16 lo, hi;\n\t"
        "cvt.rn.bf16.f32 lo, %1;\n\t"
        "cvt.rn.bf16.f32 hi, %2;\n\t"
        "mov.b32 %0, {lo, hi}; }"
        : "=r"(r) : "f"(a), "f"(b));
    return r;
}

// hi = truncated-bf16 (pure integer bit ops), lo = rn-bf16 of exact residual
__device__ __forceinline__ void split4(float4 v, uint2& hi, uint2& lo) {
    uint32_t ux = __float_as_uint(v.x), uy = __float_as_uint(v.y);
    uint32_t uz = __float_as_uint(v.z), uw = __float_as_uint(v.w);
    hi.x = (ux >> 16) | (uy & 0xFFFF0000u);
    hi.y = (uz >> 16) | (uw & 0xFFFF0000u);
    float lx = v.x - __uint_as_float(ux & 0xFFFF0000u);
    float ly = v.y - __uint_as_float(uy & 0xFFFF0000u);
    float lz = v.z - __uint_as_float(uz & 0xFFFF0000u);
    float lw = v.w - __uint_as_float(uw & 0xFFFF0000u);
    lo.x = pack_bf16x2(lx, ly);
    lo.y = pack_bf16x2(lz, lw);
}

__device__ __forceinline__ float sigm(float x) { return 1.0f / (1.0f + __expf(-x)); }
__device__ __forceinline__ float tanh_fast(float x) {
    x = fminf(15.0f, fmaxf(-15.0f, x));
    float e = __expf(2.0f * x);
    return (e - 1.0f) / (e + 1.0f);
}

// ---------------- transposes ----------------
__global__ void transpose_in_k(const float* __restrict__ img) {
    __shared__ float tile[32][33];
    const int tx = threadIdx.x, ty = threadIdx.y;
    const int b = blockIdx.z & 7, h = blockIdx.z >> 3;
    const int w0 = blockIdx.x * 32, d0 = blockIdx.y * 32;
#pragma unroll
    for (int i = 0; i < 32; i += 8) {
        int d = d0 + ty + i;
        tile[ty + i][tx] = img[(((size_t)b * DD + d) * HH + h) * WW + w0 + tx];
    }
    __syncthreads();
#pragma unroll
    for (int i = 0; i < 32; i += 8) {
        int w = w0 + ty + i;
        g_xh[((size_t)w * (HH * BB) + blockIdx.z) * DD + d0 + tx] = tile[tx][ty + i];
    }
}

__global__ void transpose_out_k(float* __restrict__ out) {
    __shared__ float tile[32][33];
    const int tx = threadIdx.x, ty = threadIdx.y;
    const int b = blockIdx.z & 7, h = blockIdx.z >> 3;
    const int w0 = blockIdx.x * 32, c0 = blockIdx.y * 32;
#pragma unroll
    for (int i = 0; i < 32; i += 8) {
        int w = w0 + ty + i;
        tile[ty + i][tx] =
            g_vout[(size_t)h * (WW * BB * 128) + ((size_t)w * BB + b) * 128 + c0 + tx];
    }
    __syncthreads();
#pragma unroll
    for (int i = 0; i < 32; i += 8) {
        int c = c0 + ty + i;
        out[(((size_t)b * 128 + c) * HH + h) * WW + w0 + tx] = tile[tx][ty + i];
    }
}

// ---------------- gx GEMM: gx[dir][token][half*128..+128) = X @ W_half^T ----------------
// mma.sync m16n8k16 bf16, 3-product hi/lo split (AhBh + AhBl + AlBh).
// Fragments loaded by direct LDS with textbook per-lane indices.
// CTA: 128 tokens x 128 gates. 8 warps: wm = warp&3 (32-token M group),
// wn = warp>>2 (64-gate N group). blockIdx.y = dir*2 + half.
// Input buffer selected on-device via VERT (device-global addresses!).
template <int K, bool VERT>
__global__ void __launch_bounds__(256, 1)
gx_gemm(const float* __restrict__ WF, const float* __restrict__ WB, int ntiles) {
    constexpr int SA = K + 8;   // row stride (bf16): 36/68 words -> quad pattern conflict-free
    extern __shared__ __nv_bfloat16 smb[];
    __nv_bfloat16* Ahi = smb;                 // 128 * SA
    __nv_bfloat16* Alo = Ahi + 128 * SA;
    __nv_bfloat16* Bhi = Alo + 128 * SA;      // 128 * SA (this CTA's gate half)
    __nv_bfloat16* Blo = Bhi + 128 * SA;

    const float* X = VERT ? g_vbuf : g_xh;    // device-side symbol reference

    const int tid = threadIdx.x;
    const int warp = tid >> 5;
    const int lane = tid & 31;
    const int wm = warp & 3;         // M group: 32 tokens
    const int wn = warp >> 2;        // N group: 64 gates
    const int half = blockIdx.y & 1;
    const int dir = blockIdx.y >> 1;

    const float* W = (dir ? WB : WF) + (size_t)half * 128 * K;
    float* gxo = g_gx + (size_t)dir * ((size_t)262144 * 256) + half * 128;

    // stationary weight half -> smem (hi/lo)
    for (int i = tid; i < 128 * K / 4; i += 256) {
        int row = i / (K / 4), c4 = (i % (K / 4)) * 4;
        float4 v = ((const float4*)W)[i];
        uint2 hi, lo;
        split4(v, hi, lo);
        *(uint2*)&Bhi[row * SA + c4] = hi;
        *(uint2*)&Blo[row * SA + c4] = lo;
    }

    const int qrow = lane >> 2;       // 0-7
    const int qk = (lane & 3) * 2;    // 0,2,4,6

    for (int ti = blockIdx.x; ti < ntiles; ti += gridDim.x) {
        const size_t token0 = (size_t)ti * 128;
        const float* Xt = X + token0 * K;

        __syncthreads();   // previous iteration's smem reads done
        for (int i = tid; i < 128 * K / 4; i += 256) {
            int row = i / (K / 4), c4 = (i % (K / 4)) * 4;
            float4 v = ((const float4*)Xt)[i];
            uint2 hi, lo;
            split4(v, hi, lo);
            *(uint2*)&Ahi[row * SA + c4] = hi;
            *(uint2*)&Alo[row * SA + c4] = lo;
        }
        __syncthreads();

        float c[2][8][4];
#pragma unroll
        for (int i = 0; i < 2; i++)
#pragma unroll
            for (int j = 0; j < 8; j++)
#pragma unroll
                for (int q = 0; q < 4; q++) c[i][j][q] = 0.0f;

#pragma unroll
        for (int kc = 0; kc < K / 16; kc++) {
            // B fragments: b0=(k0-7,n0-7), b1=(k8-15,n0-7); [2],[3] = n+8
            uint32_t Bh[4][4], Bl[4][4];
#pragma unroll
            for (int jp = 0; jp < 4; jp++) {
                int base = (wn * 64 + jp * 16 + qrow) * SA + kc * 16 + qk;
                Bh[jp][0] = *(const uint32_t*)&Bhi[base];
                Bh[jp][1] = *(const uint32_t*)&Bhi[base + 8];
                Bh[jp][2] = *(const uint32_t*)&Bhi[base + 8 * SA];
                Bh[jp][3] = *(const uint32_t*)&Bhi[base + 8 * SA + 8];
                Bl[jp][0] = *(const uint32_t*)&Blo[base];
                Bl[jp][1] = *(const uint32_t*)&Blo[base + 8];
                Bl[jp][2] = *(const uint32_t*)&Blo[base + 8 * SA];
                Bl[jp][3] = *(const uint32_t*)&Blo[base + 8 * SA + 8];
            }
#pragma unroll
            for (int ib = 0; ib < 2; ib++) {
                int base = (wm * 32 + ib * 16 + qrow) * SA + kc * 16 + qk;
                uint32_t Ah[4], Al[4];
                Ah[0] = *(const uint32_t*)&Ahi[base];               // row, k0-7
                Ah[1] = *(const uint32_t*)&Ahi[base + 8 * SA];      // row+8, k0-7
                Ah[2] = *(const uint32_t*)&Ahi[base + 8];           // row, k8-15
                Ah[3] = *(const uint32_t*)&Ahi[base + 8 * SA + 8];  // row+8, k8-15
                Al[0] = *(const uint32_t*)&Alo[base];
                Al[1] = *(const uint32_t*)&Alo[base + 8 * SA];
                Al[2] = *(const uint32_t*)&Alo[base + 8];
                Al[3] = *(const uint32_t*)&Alo[base + 8 * SA + 8];
#pragma unroll
                for (int jp = 0; jp < 4; jp++)
#pragma unroll
                    for (int h = 0; h < 2; h++) {
                        float* cc = c[ib][jp * 2 + h];
                        mma_bf16(cc, Ah, &Bh[jp][h * 2]);
                        mma_bf16(cc, Ah, &Bl[jp][h * 2]);
                        mma_bf16(cc, Al, &Bh[jp][h * 2]);
                    }
            }
        }

        // epilogue: c0,c1 -> (row, col..col+1); c2,c3 -> (row+8, col)
#pragma unroll
        for (int ib = 0; ib < 2; ib++) {
            size_t row = token0 + wm * 32 + ib * 16 + qrow;
#pragma unroll
            for (int j = 0; j < 8; j++) {
                int col = wn * 64 + j * 8 + qk;
                *(float2*)&gxo[row * 256 + col] = make_float2(c[ib][j][0], c[ib][j][1]);
                *(float2*)&gxo[(row + 8) * 256 + col] = make_float2(c[ib][j][2], c[ib][j][3]);
            }
        }
    }
}

// ---------------- lean recurrence: gates = gx_t + bias + h @ Whh^T ----------------
template <bool VERT, int T, int STOT, int NSEQ, int OT, int SDIV, int OHI>
__global__ void __launch_bounds__(512, 1)
lstm_recur(const float* __restrict__ WhhF, const float* __restrict__ bihF,
           const float* __restrict__ bhhF, const float* __restrict__ WhhB,
           const float* __restrict__ bihB, const float* __restrict__ bhhB) {
    constexpr int NT = NSEQ * 16;
    constexpr int KP = 68;
    float* outbuf = VERT ? g_vout : g_vbuf;

    extern __shared__ float sm[];
    float* Wsh = sm;                // 256 * 68
    float* insh = sm + 256 * KP;    // NSEQ * 68
    float* bsum = insh + NSEQ * KP; // 256

    const int tid = threadIdx.x;
    const int dir = blockIdx.y;
    const int s0 = blockIdx.x * NSEQ;
    const float* Whh = dir ? WhhB : WhhF;
    const float* bih = dir ? bihB : bihF;
    const float* bhh = dir ? bhhB : bhhF;
    const float* gxd = g_gx + (size_t)dir * ((size_t)262144 * 256);

    for (int i = tid; i < 256 * 64; i += NT)
        Wsh[(i >> 6) * KP + (i & 63)] = Whh[i];
    for (int i = tid; i < 256; i += NT) bsum[i] = bih[i] + bhh[i];
    for (int i = tid; i < NSEQ * 64; i += NT) insh[(i >> 6) * KP + (i & 63)] = 0.0f;

    const int jgrp = tid & 63;
    const int sgrp = tid >> 6;

    float cur[16], nxt[16];
    {
        int tt0 = dir ? (T - 1) : 0;
        const float* gp = &gxd[((size_t)tt0 * STOT + s0 + sgrp * 4) * 256 + jgrp];
#pragma unroll
        for (int ss = 0; ss < 4; ss++)
#pragma unroll
            for (int g = 0; g < 4; g++) cur[ss * 4 + g] = gp[ss * 256 + g * 64];
    }
    __syncthreads();

    float bj[4];
#pragma unroll
    for (int g = 0; g < 4; g++) bj[g] = bsum[g * 64 + jgrp];

    float creg[4] = {0.0f, 0.0f, 0.0f, 0.0f};

    const float* wp0 = &Wsh[(0 * 64 + jgrp) * KP];
    const float* wp1 = &Wsh[(1 * 64 + jgrp) * KP];
    const float* wp2 = &Wsh[(2 * 64 + jgrp) * KP];
    const float* wp3 = &Wsh[(3 * 64 + jgrp) * KP];
    const float* ip0 = &insh[(sgrp * 4 + 0) * KP];
    const float* ip1 = &insh[(sgrp * 4 + 1) * KP];
    const float* ip2 = &insh[(sgrp * 4 + 2) * KP];
    const float* ip3 = &insh[(sgrp * 4 + 3) * KP];

    for (int t = 0; t < T; t++) {
        const int tt = dir ? (T - 1 - t) : t;
        const bool havepre = (t + 1 < T);
        if (havepre) {
            int tn = dir ? (tt - 1) : (tt + 1);
            const float* gp = &gxd[((size_t)tn * STOT + s0 + sgrp * 4) * 256 + jgrp];
#pragma unroll
            for (int ss = 0; ss < 4; ss++)
#pragma unroll
                for (int g = 0; g < 4; g++) nxt[ss * 4 + g] = gp[ss * 256 + g * 64];
        }

        float acc[4][4];
#pragma unroll
        for (int ss = 0; ss < 4; ss++)
#pragma unroll
            for (int g = 0; g < 4; g++) acc[ss][g] = bj[g] + cur[ss * 4 + g];

#pragma unroll 4
        for (int k = 0; k < 64; k += 4) {
            float4 w0 = *(const float4*)(wp0 + k);
            float4 w1 = *(const float4*)(wp1 + k);
            float4 w2 = *(const float4*)(wp2 + k);
            float4 w3 = *(const float4*)(wp3 + k);
            const float* ips[4] = {ip0, ip1, ip2, ip3};
#pragma unroll
            for (int ss = 0; ss < 4; ss++) {
                float4 xv = *(const float4*)(ips[ss] + k);
                acc[ss][0] = fmaf(xv.x, w0.x, fmaf(xv.y, w0.y, fmaf(xv.z, w0.z, fmaf(xv.w, w0.w, acc[ss][0]))));
                acc[ss][1] = fmaf(xv.x, w1.x, fmaf(xv.y, w1.y, fmaf(xv.z, w1.z, fmaf(xv.w, w1.w, acc[ss][1]))));
                acc[ss][2] = fmaf(xv.x, w2.x, fmaf(xv.y, w2.y, fmaf(xv.z, w2.z, fmaf(xv.w, w2.w, acc[ss][2]))));
                acc[ss][3] = fmaf(xv.x, w3.x, fmaf(xv.y, w3.y, fmaf(xv.z, w3.z, fmaf(xv.w, w3.w, acc[ss][3]))));
            }
        }
        __syncthreads();

#pragma unroll
        for (int ss = 0; ss < 4; ss++) {
            int ls = sgrp * 4 + ss;
            int s = s0 + ls;
            float iv = sigm(acc[ss][0]);
            float fv = sigm(acc[ss][1]);
            float gv = tanh_fast(acc[ss][2]);
            float ov = sigm(acc[ss][3]);
            float c = fv * creg[ss] + iv * gv;
            creg[ss] = c;
            float hv = ov * tanh_fast(c);
            insh[ls * KP + jgrp] = hv;
            size_t oidx = (size_t)(s / SDIV) * OHI + (size_t)(s % SDIV) * 128 +
                          (size_t)tt * OT + (size_t)dir * 64 + jgrp;
            outbuf[oidx] = hv;
        }
        if (havepre) {
#pragma unroll
            for (int q = 0; q < 16; q++) cur[q] = nxt[q];
        }
        __syncthreads();
    }
}

// ---------------- launch ----------------
extern "C" void kernel_launch(void* const* d_in, const int* in_sizes, int n_in,
                              void* d_out, int out_size) {
    const float* img    = (const float*)d_in[0];
    const float* hWihF  = (const float*)d_in[1];
    const float* hWhhF  = (const float*)d_in[2];
    const float* hbihF  = (const float*)d_in[3];
    const float* hbhhF  = (const float*)d_in[4];
    const float* hWihB  = (const float*)d_in[5];
    const float* hWhhB  = (const float*)d_in[6];
    const float* hbihB  = (const float*)d_in[7];
    const float* hbhhB  = (const float*)d_in[8];
    const float* vWihF  = (const float*)d_in[9];
    const float* vWhhF  = (const float*)d_in[10];
    const float* vbihF  = (const float*)d_in[11];
    const float* vbhhF  = (const float*)d_in[12];
    const float* vWihB  = (const float*)d_in[13];
    const float* vWhhB  = (const float*)d_in[14];
    const float* vbihB  = (const float*)d_in[15];
    const float* vbhhB  = (const float*)d_in[16];
    float* out = (float*)d_out;

    auto hG = gx_gemm<64, false>;
    auto vG = gx_gemm<128, true>;
    auto hR = lstm_recur<false, 256, 1024, 16, 1024, 8, 262144>;
    auto vR = lstm_recur<true, 128, 2048, 32, 262144, (1 << 28), 0>;

    const int smemHG = 4 * 128 * (64 + 8) * 2;            //  73,728 B
    const int smemVG = 4 * 128 * (128 + 8) * 2;           // 139,264 B
    const int smemHR = (256 * 68 + 16 * 68 + 256) * 4;    //  75,008 B
    const int smemVR = (256 * 68 + 32 * 68 + 256) * 4;    //  79,360 B
    cudaFuncSetAttribute(hG, cudaFuncAttributeMaxDynamicSharedMemorySize, smemHG);
    cudaFuncSetAttribute(vG, cudaFuncAttributeMaxDynamicSharedMemorySize, smemVG);
    cudaFuncSetAttribute(hR, cudaFuncAttributeMaxDynamicSharedMemorySize, smemHR);
    cudaFuncSetAttribute(vR, cudaFuncAttributeMaxDynamicSharedMemorySize, smemVR);

    // 1) img -> g_xh
    transpose_in_k<<<dim3(WW / 32, DD / 32, HH * BB), dim3(32, 8)>>>(img);

    // 2) gxh = g_xh @ hWih^T   (2048 token tiles; y = dir*2+half; 148 CTAs)
    hG<<<dim3(37, 4), 256, smemHG>>>(hWihF, hWihB, 2048);

    // 3) horizontal recurrence -> g_vbuf
    hR<<<dim3(64, 2), 256, smemHR>>>(hWhhF, hbihF, hbhhF, hWhhB, hbihB, hbhhB);

    // 4) gxv = g_vbuf @ vWih^T
    vG<<<dim3(37, 4), 256, smemVG>>>(vWihF, vWihB, 2048);

    // 5) vertical recurrence -> g_vout
    vR<<<dim3(64, 2), 512, smemVR>>>(vWhhF, vbihF, vbhhF, vWhhB, vbihB, vbhhB);

    // 6) g_vout -> out
    transpose_out_k<<<dim3(WW / 32, 128 / 32, HH * BB), dim3(32, 8)>>>(out);
}

// round 9
// speedup vs baseline: 1.6176x; 1.2049x over previous
#include <cuda_runtime.h>
#include <cuda_bf16.h>
#include <math.h>
#include <stdint.h>

#define BB 8
#define DD 64
#define HH 128
#define WW 256

// ---------------- scratch (static device globals) ----------------
// ONLY referenced from device code (host-side symbol use = host shadow under ATS!)
__device__ float g_xh[(size_t)WW * HH * BB * DD];       // [w][h*8+b][64]
__device__ float g_vbuf[(size_t)HH * WW * BB * 128];    // [h][w*8+b][128]
__device__ float g_vout[(size_t)HH * WW * BB * 128];    // [h][w*8+b][128]
__device__ float g_gx[(size_t)2 * 262144 * 256];        // [dir][token][permuted gate 4j+g], bias included

__device__ __forceinline__ uint32_t smem_u32(const void* p) {
    uint32_t a;
    asm("{ .reg .u64 t; cvta.to.shared.u64 t, %1; cvt.u32.u64 %0, t; }" : "=r"(a) : "l"(p));
    return a;
}

__device__ __forceinline__ void cp_async16(void* dst, const void* src) {
    asm volatile("cp.async.cg.shared.global [%0], [%1], 16;"
                 :: "r"(smem_u32(dst)), "l"(src) : "memory");
}

__device__ __forceinline__ void mma_bf16(float* c, const uint32_t* a, const uint32_t* b) {
    asm volatile(
        "mma.sync.aligned.m16n8k16.row.col.f32.bf16.bf16.f32 "
        "{%0,%1,%2,%3}, {%4,%5,%6,%7}, {%8,%9}, {%0,%1,%2,%3};"
        : "+f"(c[0]), "+f"(c[1]), "+f"(c[2]), "+f"(c[3])
        : "r"(a[0]), "r"(a[1]), "r"(a[2]), "r"(a[3]), "r"(b[0]), "r"(b[1]));
}

__device__ __forceinline__ uint32_t pack_bf16x2(float a, float b) {
    uint32_t r;
    asm("{ .reg .b16 lo, hi;\n\t"
        "cvt.rn.bf16.f32 lo, %1;\n\t"
        "cvt.rn.bf16.f32 hi, %2;\n\t"
        "mov.b32 %0, {lo, hi}; }"
        : "=r"(r) : "f"(a), "f"(b));
    return r;
}

// hi = truncated-bf16 (integer bit ops), lo = rn-bf16 of exact residual
__device__ __forceinline__ void split4(float4 v, uint2& hi, uint2& lo) {
    uint32_t ux = __float_as_uint(v.x), uy = __float_as_uint(v.y);
    uint32_t uz = __float_as_uint(v.z), uw = __float_as_uint(v.w);
    hi.x = (ux >> 16) | (uy & 0xFFFF0000u);
    hi.y = (uz >> 16) | (uw & 0xFFFF0000u);
    float lx = v.x - __uint_as_float(ux & 0xFFFF0000u);
    float ly = v.y - __uint_as_float(uy & 0xFFFF0000u);
    float lz = v.z - __uint_as_float(uz & 0xFFFF0000u);
    float lw = v.w - __uint_as_float(uw & 0xFFFF0000u);
    lo.x = pack_bf16x2(lx, ly);
    lo.y = pack_bf16x2(lz, lw);
}

__device__ __forceinline__ void split1(float x, uint16_t& h, uint16_t& l) {
    uint32_t u = __float_as_uint(x);
    h = (uint16_t)(u >> 16);
    float r = x - __uint_as_float(u & 0xFFFF0000u);
    uint16_t lb;
    asm("cvt.rn.bf16.f32 %0, %1;" : "=h"(lb) : "f"(r));
    l = lb;
}

__device__ __forceinline__ float sigm(float x) { return 1.0f / (1.0f + __expf(-x)); }
__device__ __forceinline__ float tanh_fast(float x) {
    x = fminf(15.0f, fmaxf(-15.0f, x));
    float e = __expf(2.0f * x);
    return (e - 1.0f) / (e + 1.0f);
}

// ---------------- transposes ----------------
__global__ void transpose_in_k(const float* __restrict__ img) {
    __shared__ float tile[32][33];
    const int tx = threadIdx.x, ty = threadIdx.y;
    const int b = blockIdx.z & 7, h = blockIdx.z >> 3;
    const int w0 = blockIdx.x * 32, d0 = blockIdx.y * 32;
#pragma unroll
    for (int i = 0; i < 32; i += 8) {
        int d = d0 + ty + i;
        tile[ty + i][tx] = img[(((size_t)b * DD + d) * HH + h) * WW + w0 + tx];
    }
    __syncthreads();
#pragma unroll
    for (int i = 0; i < 32; i += 8) {
        int w = w0 + ty + i;
        g_xh[((size_t)w * (HH * BB) + blockIdx.z) * DD + d0 + tx] = tile[tx][ty + i];
    }
}

__global__ void transpose_out_k(float* __restrict__ out) {
    __shared__ float tile[32][33];
    const int tx = threadIdx.x, ty = threadIdx.y;
    const int b = blockIdx.z & 7, h = blockIdx.z >> 3;
    const int w0 = blockIdx.x * 32, c0 = blockIdx.y * 32;
#pragma unroll
    for (int i = 0; i < 32; i += 8) {
        int w = w0 + ty + i;
        tile[ty + i][tx] =
            g_vout[(size_t)h * (WW * BB * 128) + ((size_t)w * BB + b) * 128 + c0 + tx];
    }
    __syncthreads();
#pragma unroll
    for (int i = 0; i < 32; i += 8) {
        int c = c0 + ty + i;
        out[(((size_t)b * 128 + c) * HH + h) * WW + w0 + tx] = tile[tx][ty + i];
    }
}

// ---------------- gx GEMM: gx[dir][token][perm 4j+g] = X @ Wih^T + bias ----------------
// mma.sync bf16 3-product split; weights permuted to gate-interleaved order;
// cp.async double-stage pipeline. CTA: 128 tokens x 128 perm-cols (hiddens [32h,32h+32)).
template <int K, bool VERT>
__global__ void __launch_bounds__(256, 1)
gx_gemm(const float* __restrict__ WF, const float* __restrict__ WB,
        const float* __restrict__ bihF, const float* __restrict__ bhhF,
        const float* __restrict__ bihB, const float* __restrict__ bhhB, int ntiles) {
    constexpr int SA = K + 8;
    extern __shared__ float smf[];
    float* stage = smf;                               // 128*K fp32
    uint16_t* Ahi = (uint16_t*)(stage + 128 * K);     // 128*SA each
    uint16_t* Alo = Ahi + 128 * SA;
    uint16_t* Bhi = Alo + 128 * SA;
    uint16_t* Blo = Bhi + 128 * SA;
    float* bsum = (float*)(Blo + 128 * SA);           // 128

    const float* X = VERT ? g_vbuf : g_xh;

    const int tid = threadIdx.x;
    const int warp = tid >> 5;
    const int lane = tid & 31;
    const int wm = warp & 3;         // M group: 32 tokens
    const int wn = warp >> 2;        // N group: 64 perm-cols
    const int half = blockIdx.y & 1;
    const int dir = blockIdx.y >> 1;

    const float* W = dir ? WB : WF;
    const float* bih = dir ? bihB : bihF;
    const float* bhh = dir ? bhhB : bhhF;
    float* gxo = g_gx + (size_t)dir * ((size_t)262144 * 256) + half * 128;

    // permuted stationary weights: smem row rr <-> perm col 128*half+rr;
    // source W row = (rr&3)*64 + 32*half + (rr>>2)
    for (int i = tid; i < 128 * (K / 4); i += 256) {
        int rr = i / (K / 4), c16 = i % (K / 4);
        int src = (rr & 3) * 64 + 32 * half + (rr >> 2);
        float4 v = ((const float4*)W)[src * (K / 4) + c16];
        uint2 hi, lo;
        split4(v, hi, lo);
        *(uint2*)&Bhi[rr * SA + c16 * 4] = hi;
        *(uint2*)&Blo[rr * SA + c16 * 4] = lo;
    }
    if (tid < 128) {
        int G = (tid & 3) * 64 + 32 * half + (tid >> 2);
        bsum[tid] = bih[G] + bhh[G];
    }

    const int qrow = lane >> 2;
    const int qk = (lane & 3) * 2;

    int ti = blockIdx.x;
    // prolog: stage tile ti
    {
        const float* Xt = X + (size_t)ti * 128 * K;
        for (int i = tid; i < 128 * K / 4; i += 256)
            cp_async16(stage + i * 4, Xt + i * 4);
        asm volatile("cp.async.commit_group;" ::: "memory");
    }

    for (; ti < ntiles; ti += gridDim.x) {
        asm volatile("cp.async.wait_group 0;" ::: "memory");
        __syncthreads();   // stage ready AND prior bf16 reads done
        // convert stage -> hi/lo bf16 smem
        for (int i = tid; i < 128 * K / 4; i += 256) {
            int row = i / (K / 4), c4 = (i % (K / 4)) * 4;
            float4 v = *(float4*)&stage[i * 4];
            uint2 hi, lo;
            split4(v, hi, lo);
            *(uint2*)&Ahi[row * SA + c4] = hi;
            *(uint2*)&Alo[row * SA + c4] = lo;
        }
        __syncthreads();
        // stage now free: start next tile's loads (overlaps with mma below)
        if (ti + (int)gridDim.x < ntiles) {
            const float* Xt = X + (size_t)(ti + gridDim.x) * 128 * K;
            for (int i = tid; i < 128 * K / 4; i += 256)
                cp_async16(stage + i * 4, Xt + i * 4);
            asm volatile("cp.async.commit_group;" ::: "memory");
        }

        float c[2][8][4];
#pragma unroll
        for (int i = 0; i < 2; i++)
#pragma unroll
            for (int j = 0; j < 8; j++)
#pragma unroll
                for (int q = 0; q < 4; q++) c[i][j][q] = 0.0f;

#pragma unroll
        for (int kc = 0; kc < K / 16; kc++) {
            uint32_t Bh[4][4], Bl[4][4];
#pragma unroll
            for (int jp = 0; jp < 4; jp++) {
                int base = (wn * 64 + jp * 16 + qrow) * SA + kc * 16 + qk;
                Bh[jp][0] = *(const uint32_t*)&Bhi[base];
                Bh[jp][1] = *(const uint32_t*)&Bhi[base + 8];
                Bh[jp][2] = *(const uint32_t*)&Bhi[base + 8 * SA];
                Bh[jp][3] = *(const uint32_t*)&Bhi[base + 8 * SA + 8];
                Bl[jp][0] = *(const uint32_t*)&Blo[base];
                Bl[jp][1] = *(const uint32_t*)&Blo[base + 8];
                Bl[jp][2] = *(const uint32_t*)&Blo[base + 8 * SA];
                Bl[jp][3] = *(const uint32_t*)&Blo[base + 8 * SA + 8];
            }
#pragma unroll
            for (int ib = 0; ib < 2; ib++) {
                int base = (wm * 32 + ib * 16 + qrow) * SA + kc * 16 + qk;
                uint32_t Ah[4], Al[4];
                Ah[0] = *(const uint32_t*)&Ahi[base];
                Ah[1] = *(const uint32_t*)&Ahi[base + 8 * SA];
                Ah[2] = *(const uint32_t*)&Ahi[base + 8];
                Ah[3] = *(const uint32_t*)&Ahi[base + 8 * SA + 8];
                Al[0] = *(const uint32_t*)&Alo[base];
                Al[1] = *(const uint32_t*)&Alo[base + 8 * SA];
                Al[2] = *(const uint32_t*)&Alo[base + 8];
                Al[3] = *(const uint32_t*)&Alo[base + 8 * SA + 8];
#pragma unroll
                for (int jp = 0; jp < 4; jp++)
#pragma unroll
                    for (int h = 0; h < 2; h++) {
                        float* cc = c[ib][jp * 2 + h];
                        mma_bf16(cc, Ah, &Bh[jp][h * 2]);
                        mma_bf16(cc, Ah, &Bl[jp][h * 2]);
                        mma_bf16(cc, Al, &Bh[jp][h * 2]);
                    }
            }
        }

        const size_t token0 = (size_t)ti * 128;
#pragma unroll
        for (int ib = 0; ib < 2; ib++) {
            size_t row = token0 + wm * 32 + ib * 16 + qrow;
#pragma unroll
            for (int j = 0; j < 8; j++) {
                int col = wn * 64 + j * 8 + qk;
                float b0 = bsum[col], b1 = bsum[col + 1];
                *(float2*)&gxo[row * 256 + col] =
                    make_float2(c[ib][j][0] + b0, c[ib][j][1] + b1);
                *(float2*)&gxo[(row + 8) * 256 + col] =
                    make_float2(c[ib][j][2] + b0, c[ib][j][3] + b1);
            }
        }
        __syncthreads();   // all epilogue smem reads (bsum) trivial; protects bf16 overwrite next iter
    }
}

// ---------------- mma recurrence: gates_t = gx_t(+bias) + h @ Whh'^T ----------------
// Whh permuted (perm row 4j+g) hi/lo fragments hoisted into registers.
// 256 thr = 8 warps; warp wn owns 32 perm-cols (8 hiddens). M = NSEQ (16/32).
// gate exchange via shfl.xor(1); h state hi/lo bf16 in smem; coalesced out via stage.
template <bool VERT, int T, int STOT, int NSEQ, int OT, int SDIV, int OHI>
__global__ void __launch_bounds__(256, 1)
lstm_recur_mma(const float* __restrict__ WhhF, const float* __restrict__ WhhB) {
    constexpr int MT = NSEQ / 16;
    constexpr int SW = 72;
    extern __shared__ char smraw[];
    uint16_t* WHi = (uint16_t*)smraw;            // 256*SW (weight staging, transient)
    uint16_t* WLo = WHi + 256 * SW;
    uint16_t* hHi = (uint16_t*)smraw;            // NSEQ*SW (aliased after staging)
    uint16_t* hLo = hHi + NSEQ * SW;
    float* stg = (float*)(hLo + NSEQ * SW);      // NSEQ*64 fp32 out staging

    const int tid = threadIdx.x;
    const int wn = tid >> 5;
    const int lane = tid & 31;
    const int qrow = lane >> 2;
    const int qk = (lane & 3) * 2;
    const int par = lane & 1;
    const int dir = blockIdx.y;
    const int s0 = blockIdx.x * NSEQ;

    const float* Whh = dir ? WhhB : WhhF;
    const float* gxd = g_gx + (size_t)dir * ((size_t)262144 * 256);
    float* outbuf = VERT ? g_vout : g_vbuf;

    // stage permuted Whh hi/lo
    for (int i = tid; i < 256 * 16; i += 256) {
        int rr = i >> 4, c16 = i & 15;
        int src = (rr & 3) * 64 + (rr >> 2);
        float4 v = ((const float4*)Whh)[src * 16 + c16];
        uint2 hi, lo;
        split4(v, hi, lo);
        *(uint2*)&WHi[rr * SW + c16 * 4] = hi;
        *(uint2*)&WLo[rr * SW + c16 * 4] = lo;
    }
    __syncthreads();

    // hoist B fragments into registers (stationary for whole pass)
    uint32_t Bh[2][4][4], Bl[2][4][4];   // [jp16][kc][reg]
#pragma unroll
    for (int jp = 0; jp < 2; jp++)
#pragma unroll
        for (int kc = 0; kc < 4; kc++) {
            int base = (wn * 32 + jp * 16 + qrow) * SW + kc * 16 + qk;
            Bh[jp][kc][0] = *(const uint32_t*)&WHi[base];
            Bh[jp][kc][1] = *(const uint32_t*)&WHi[base + 8];
            Bh[jp][kc][2] = *(const uint32_t*)&WHi[base + 8 * SW];
            Bh[jp][kc][3] = *(const uint32_t*)&WHi[base + 8 * SW + 8];
            Bl[jp][kc][0] = *(const uint32_t*)&WLo[base];
            Bl[jp][kc][1] = *(const uint32_t*)&WLo[base + 8];
            Bl[jp][kc][2] = *(const uint32_t*)&WLo[base + 8 * SW];
            Bl[jp][kc][3] = *(const uint32_t*)&WLo[base + 8 * SW + 8];
        }
    __syncthreads();   // done reading staging; reuse as h state

    for (int i = tid; i < NSEQ * SW; i += 256) { hHi[i] = 0; hLo[i] = 0; }

    // gx accumulator regs for first step
    float cur[MT][2][2][4];
    {
        int tt0 = dir ? (T - 1) : 0;
#pragma unroll
        for (int mt = 0; mt < MT; mt++)
#pragma unroll
            for (int jp = 0; jp < 2; jp++)
#pragma unroll
                for (int h8 = 0; h8 < 2; h8++) {
                    const float* p = gxd +
                        ((size_t)tt0 * STOT + s0 + mt * 16 + qrow) * 256 +
                        (wn * 32 + jp * 16 + h8 * 8 + qk);
                    float2 ab = *(const float2*)p;
                    float2 cd = *(const float2*)(p + 8 * 256);
                    cur[mt][jp][h8][0] = ab.x; cur[mt][jp][h8][1] = ab.y;
                    cur[mt][jp][h8][2] = cd.x; cur[mt][jp][h8][3] = cd.y;
                }
    }
    __syncthreads();

    float creg[MT][2][2];
#pragma unroll
    for (int mt = 0; mt < MT; mt++)
#pragma unroll
        for (int jp = 0; jp < 2; jp++)
#pragma unroll
            for (int h8 = 0; h8 < 2; h8++) creg[mt][jp][h8] = 0.0f;

    for (int t = 0; t < T; t++) {
        const int tt = dir ? (T - 1 - t) : t;
        const bool havepre = (t + 1 < T);
        float nxt[MT][2][2][4];
        if (havepre) {
            int tn = dir ? (tt - 1) : (tt + 1);
#pragma unroll
            for (int mt = 0; mt < MT; mt++)
#pragma unroll
                for (int jp = 0; jp < 2; jp++)
#pragma unroll
                    for (int h8 = 0; h8 < 2; h8++) {
                        const float* p = gxd +
                            ((size_t)tn * STOT + s0 + mt * 16 + qrow) * 256 +
                            (wn * 32 + jp * 16 + h8 * 8 + qk);
                        float2 ab = *(const float2*)p;
                        float2 cd = *(const float2*)(p + 8 * 256);
                        nxt[mt][jp][h8][0] = ab.x; nxt[mt][jp][h8][1] = ab.y;
                        nxt[mt][jp][h8][2] = cd.x; nxt[mt][jp][h8][3] = cd.y;
                    }
        }

        // accumulate h @ Whh'^T into cur (3-product split)
#pragma unroll
        for (int kc = 0; kc < 4; kc++) {
            uint32_t Ah[MT][4], Al[MT][4];
#pragma unroll
            for (int mt = 0; mt < MT; mt++) {
                int base = (mt * 16 + qrow) * SW + kc * 16 + qk;
                Ah[mt][0] = *(const uint32_t*)&hHi[base];
                Ah[mt][1] = *(const uint32_t*)&hHi[base + 8 * SW];
                Ah[mt][2] = *(const uint32_t*)&hHi[base + 8];
                Ah[mt][3] = *(const uint32_t*)&hHi[base + 8 * SW + 8];
                Al[mt][0] = *(const uint32_t*)&hLo[base];
                Al[mt][1] = *(const uint32_t*)&hLo[base + 8 * SW];
                Al[mt][2] = *(const uint32_t*)&hLo[base + 8];
                Al[mt][3] = *(const uint32_t*)&hLo[base + 8 * SW + 8];
            }
#pragma unroll
            for (int mt = 0; mt < MT; mt++)
#pragma unroll
                for (int jp = 0; jp < 2; jp++)
#pragma unroll
                    for (int h8 = 0; h8 < 2; h8++) {
                        float* cc = cur[mt][jp][h8];
                        mma_bf16(cc, Ah[mt], &Bh[jp][kc][h8 * 2]);
                        mma_bf16(cc, Ah[mt], &Bl[jp][kc][h8 * 2]);
                        mma_bf16(cc, Al[mt], &Bh[jp][kc][h8 * 2]);
                    }
        }

        // gate exchange + activations (register/shuffle only)
        float hval[MT][2][2];
#pragma unroll
        for (int mt = 0; mt < MT; mt++)
#pragma unroll
            for (int jp = 0; jp < 2; jp++)
#pragma unroll
                for (int h8 = 0; h8 < 2; h8++) {
                    float* cc = cur[mt][jp][h8];
                    float s0v = par ? cc[0] : cc[2];
                    float s1v = par ? cc[1] : cc[3];
                    float r0 = __shfl_xor_sync(0xFFFFFFFFu, s0v, 1);
                    float r1 = __shfl_xor_sync(0xFFFFFFFFu, s1v, 1);
                    float iv, fv, gv, ov;
                    if (!par) { iv = cc[0]; fv = cc[1]; gv = r0; ov = r1; }
                    else      { iv = r0;    fv = r1;    gv = cc[2]; ov = cc[3]; }
                    float cst = sigm(fv) * creg[mt][jp][h8] + sigm(iv) * tanh_fast(gv);
                    creg[mt][jp][h8] = cst;
                    hval[mt][jp][h8] = sigm(ov) * tanh_fast(cst);
                }

        __syncthreads();   // all warps done reading h smem
#pragma unroll
        for (int mt = 0; mt < MT; mt++)
#pragma unroll
            for (int jp = 0; jp < 2; jp++)
#pragma unroll
                for (int h8 = 0; h8 < 2; h8++) {
                    int j = wn * 8 + jp * 4 + h8 * 2 + (qk >> 2);
                    int myrow = mt * 16 + qrow + par * 8;
                    float hv = hval[mt][jp][h8];
                    uint16_t hb, lb;
                    split1(hv, hb, lb);
                    hHi[myrow * SW + j] = hb;
                    hLo[myrow * SW + j] = lb;
                    stg[myrow * 64 + j] = hv;
                }
        __syncthreads();   // h + stage visible

        // coalesced output store
#pragma unroll
        for (int e = 0; e < MT; e++) {
            int idx4 = tid + e * 256;
            int ls = idx4 >> 4, jj = (idx4 & 15) << 2;
            float4 v = *(const float4*)&stg[ls * 64 + jj];
            int s = s0 + ls;
            size_t addr = (size_t)(s / SDIV) * OHI + (size_t)(s % SDIV) * 128 +
                          (size_t)tt * OT + (size_t)dir * 64 + jj;
            *(float4*)&outbuf[addr] = v;
        }

        if (havepre) {
#pragma unroll
            for (int mt = 0; mt < MT; mt++)
#pragma unroll
                for (int jp = 0; jp < 2; jp++)
#pragma unroll
                    for (int h8 = 0; h8 < 2; h8++)
#pragma unroll
                        for (int q = 0; q < 4; q++)
                            cur[mt][jp][h8][q] = nxt[mt][jp][h8][q];
        }
    }
}

// ---------------- launch ----------------
extern "C" void kernel_launch(void* const* d_in, const int* in_sizes, int n_in,
                              void* d_out, int out_size) {
    const float* img    = (const float*)d_in[0];
    const float* hWihF  = (const float*)d_in[1];
    const float* hWhhF  = (const float*)d_in[2];
    const float* hbihF  = (const float*)d_in[3];
    const float* hbhhF  = (const float*)d_in[4];
    const float* hWihB  = (const float*)d_in[5];
    const float* hWhhB  = (const float*)d_in[6];
    const float* hbihB  = (const float*)d_in[7];
    const float* hbhhB  = (const float*)d_in[8];
    const float* vWihF  = (const float*)d_in[9];
    const float* vWhhF  = (const float*)d_in[10];
    const float* vbihF  = (const float*)d_in[11];
    const float* vbhhF  = (const float*)d_in[12];
    const float* vWihB  = (const float*)d_in[13];
    const float* vWhhB  = (const float*)d_in[14];
    const float* vbihB  = (const float*)d_in[15];
    const float* vbhhB  = (const float*)d_in[16];
    float* out = (float*)d_out;

    auto hG = gx_gemm<64, false>;
    auto vG = gx_gemm<128, true>;
    auto hR = lstm_recur_mma<false, 256, 1024, 16, 1024, 8, 262144>;
    auto vR = lstm_recur_mma<true, 128, 2048, 32, 262144, (1 << 28), 0>;

    const int smemHG = 128 * 64 * 4 + 4 * 128 * (64 + 8) * 2 + 512;    // 107,008 B
    const int smemVG = 128 * 128 * 4 + 4 * 128 * (128 + 8) * 2 + 512;  // 205,312 B
    const int smemR = 2 * 256 * 72 * 2;                                //  73,728 B
    cudaFuncSetAttribute(hG, cudaFuncAttributeMaxDynamicSharedMemorySize, smemHG);
    cudaFuncSetAttribute(vG, cudaFuncAttributeMaxDynamicSharedMemorySize, smemVG);
    cudaFuncSetAttribute(hR, cudaFuncAttributeMaxDynamicSharedMemorySize, smemR);
    cudaFuncSetAttribute(vR, cudaFuncAttributeMaxDynamicSharedMemorySize, smemR);

    // 1) img -> g_xh
    transpose_in_k<<<dim3(WW / 32, DD / 32, HH * BB), dim3(32, 8)>>>(img);

    // 2) gxh (permuted, bias folded)
    hG<<<dim3(37, 4), 256, smemHG>>>(hWihF, hWihB, hbihF, hbhhF, hbihB, hbhhB, 2048);

    // 3) horizontal mma recurrence -> g_vbuf
    hR<<<dim3(64, 2), 256, smemR>>>(hWhhF, hWhhB);

    // 4) gxv
    vG<<<dim3(37, 4), 256, smemVG>>>(vWihF, vWihB, vbihF, vbhhF, vbihB, vbhhB, 2048);

    // 5) vertical mma recurrence -> g_vout
    vR<<<dim3(64, 2), 256, smemR>>>(vWhhF, vWhhB);

    // 6) g_vout -> out
    transpose_out_k<<<dim3(WW / 32, 128 / 32, HH * BB), dim3(32, 8)>>>(out);
}

// round 10
// speedup vs baseline: 1.7435x; 1.0779x over previous
#include <cuda_runtime.h>
#include <cuda_bf16.h>
#include <math.h>
#include <stdint.h>

#define BB 8
#define DD 64
#define HH 128
#define WW 256

// ---------------- scratch (static device globals) ----------------
// ONLY referenced from device code (host-side symbol use = host shadow under ATS!)
__device__ float g_xh[(size_t)WW * HH * BB * DD];       // [w][h*8+b][64]
__device__ float g_vbuf[(size_t)HH * WW * BB * 128];    // [h][w*8+b][128]
__device__ float g_vout[(size_t)HH * WW * BB * 128];    // [h][w*8+b][128]
__device__ float g_gx[(size_t)2 * 262144 * 256];        // [dir][token][perm gate 4j+g], bias folded

__device__ __forceinline__ uint32_t smem_u32(const void* p) {
    uint32_t a;
    asm("{ .reg .u64 t; cvta.to.shared.u64 t, %1; cvt.u32.u64 %0, t; }" : "=r"(a) : "l"(p));
    return a;
}

__device__ __forceinline__ void cp_async16(void* dst, const void* src) {
    asm volatile("cp.async.cg.shared.global [%0], [%1], 16;"
                 :: "r"(smem_u32(dst)), "l"(src) : "memory");
}

__device__ __forceinline__ void mma_bf16(float* c, const uint32_t* a, const uint32_t* b) {
    asm volatile(
        "mma.sync.aligned.m16n8k16.row.col.f32.bf16.bf16.f32 "
        "{%0,%1,%2,%3}, {%4,%5,%6,%7}, {%8,%9}, {%0,%1,%2,%3};"
        : "+f"(c[0]), "+f"(c[1]), "+f"(c[2]), "+f"(c[3])
        : "r"(a[0]), "r"(a[1]), "r"(a[2]), "r"(a[3]), "r"(b[0]), "r"(b[1]));
}

__device__ __forceinline__ uint32_t pack_bf16x2(float a, float b) {
    uint32_t r;
    asm("{ .reg .b16 lo, hi;\n\t"
        "cvt.rn.bf16.f32 lo, %1;\n\t"
        "cvt.rn.bf16.f32 hi, %2;\n\t"
        "mov.b32 %0, {lo, hi}; }"
        : "=r"(r) : "f"(a), "f"(b));
    return r;
}

// hi = truncated-bf16 (integer bit ops), lo = rn-bf16 of exact residual
__device__ __forceinline__ void split4(float4 v, uint2& hi, uint2& lo) {
    uint32_t ux = __float_as_uint(v.x), uy = __float_as_uint(v.y);
    uint32_t uz = __float_as_uint(v.z), uw = __float_as_uint(v.w);
    hi.x = (ux >> 16) | (uy & 0xFFFF0000u);
    hi.y = (uz >> 16) | (uw & 0xFFFF0000u);
    float lx = v.x - __uint_as_float(ux & 0xFFFF0000u);
    float ly = v.y - __uint_as_float(uy & 0xFFFF0000u);
    float lz = v.z - __uint_as_float(uz & 0xFFFF0000u);
    float lw = v.w - __uint_as_float(uw & 0xFFFF0000u);
    lo.x = pack_bf16x2(lx, ly);
    lo.y = pack_bf16x2(lz, lw);
}

__device__ __forceinline__ void split1(float x, uint16_t& h, uint16_t& l) {
    uint32_t u = __float_as_uint(x);
    h = (uint16_t)(u >> 16);
    float r = x - __uint_as_float(u & 0xFFFF0000u);
    uint16_t lb;
    asm("cvt.rn.bf16.f32 %0, %1;" : "=h"(lb) : "f"(r));
    l = lb;
}

__device__ __forceinline__ float sigm(float x) { return 1.0f / (1.0f + __expf(-x)); }
__device__ __forceinline__ float tanh_fast(float x) {
    x = fminf(15.0f, fmaxf(-15.0f, x));
    float e = __expf(2.0f * x);
    return (e - 1.0f) / (e + 1.0f);
}

// capture-alignment probe: shifts the ncu -c 1 capture window onto the
// recurrence kernel (launch #4). Does nothing.
__global__ void probe_k() {}

// ---------------- transposes ----------------
__global__ void transpose_in_k(const float* __restrict__ img) {
    __shared__ float tile[32][33];
    const int tx = threadIdx.x, ty = threadIdx.y;
    const int b = blockIdx.z & 7, h = blockIdx.z >> 3;
    const int w0 = blockIdx.x * 32, d0 = blockIdx.y * 32;
#pragma unroll
    for (int i = 0; i < 32; i += 8) {
        int d = d0 + ty + i;
        tile[ty + i][tx] = img[(((size_t)b * DD + d) * HH + h) * WW + w0 + tx];
    }
    __syncthreads();
#pragma unroll
    for (int i = 0; i < 32; i += 8) {
        int w = w0 + ty + i;
        g_xh[((size_t)w * (HH * BB) + blockIdx.z) * DD + d0 + tx] = tile[tx][ty + i];
    }
}

__global__ void transpose_out_k(float* __restrict__ out) {
    __shared__ float tile[32][33];
    const int tx = threadIdx.x, ty = threadIdx.y;
    const int b = blockIdx.z & 7, h = blockIdx.z >> 3;
    const int w0 = blockIdx.x * 32, c0 = blockIdx.y * 32;
#pragma unroll
    for (int i = 0; i < 32; i += 8) {
        int w = w0 + ty + i;
        tile[ty + i][tx] =
            g_vout[(size_t)h * (WW * BB * 128) + ((size_t)w * BB + b) * 128 + c0 + tx];
    }
    __syncthreads();
#pragma unroll
    for (int i = 0; i < 32; i += 8) {
        int c = c0 + ty + i;
        out[(((size_t)b * 128 + c) * HH + h) * WW + w0 + tx] = tile[tx][ty + i];
    }
}

// ---------------- gx GEMM: gx[dir][token][perm 4j+g] = X @ Wih^T + bias ----------------
template <int K, bool VERT>
__global__ void __launch_bounds__(256, 1)
gx_gemm(const float* __restrict__ WF, const float* __restrict__ WB,
        const float* __restrict__ bihF, const float* __restrict__ bhhF,
        const float* __restrict__ bihB, const float* __restrict__ bhhB, int ntiles) {
    constexpr int SA = K + 8;
    extern __shared__ float smf[];
    float* stage = smf;                               // 128*K fp32
    uint16_t* Ahi = (uint16_t*)(stage + 128 * K);     // 128*SA each
    uint16_t* Alo = Ahi + 128 * SA;
    uint16_t* Bhi = Alo + 128 * SA;
    uint16_t* Blo = Bhi + 128 * SA;
    float* bsum = (float*)(Blo + 128 * SA);           // 128

    const float* X = VERT ? g_vbuf : g_xh;

    const int tid = threadIdx.x;
    const int warp = tid >> 5;
    const int lane = tid & 31;
    const int wm = warp & 3;
    const int wn = warp >> 2;
    const int half = blockIdx.y & 1;
    const int dir = blockIdx.y >> 1;

    const float* W = dir ? WB : WF;
    const float* bih = dir ? bihB : bihF;
    const float* bhh = dir ? bhhB : bhhF;
    float* gxo = g_gx + (size_t)dir * ((size_t)262144 * 256) + half * 128;

    for (int i = tid; i < 128 * (K / 4); i += 256) {
        int rr = i / (K / 4), c16 = i % (K / 4);
        int src = (rr & 3) * 64 + 32 * half + (rr >> 2);
        float4 v = ((const float4*)W)[src * (K / 4) + c16];
        uint2 hi, lo;
        split4(v, hi, lo);
        *(uint2*)&Bhi[rr * SA + c16 * 4] = hi;
        *(uint2*)&Blo[rr * SA + c16 * 4] = lo;
    }
    if (tid < 128) {
        int G = (tid & 3) * 64 + 32 * half + (tid >> 2);
        bsum[tid] = bih[G] + bhh[G];
    }

    const int qrow = lane >> 2;
    const int qk = (lane & 3) * 2;

    int ti = blockIdx.x;
    {
        const float* Xt = X + (size_t)ti * 128 * K;
        for (int i = tid; i < 128 * K / 4; i += 256)
            cp_async16(stage + i * 4, Xt + i * 4);
        asm volatile("cp.async.commit_group;" ::: "memory");
    }

    for (; ti < ntiles; ti += gridDim.x) {
        asm volatile("cp.async.wait_group 0;" ::: "memory");
        __syncthreads();
        for (int i = tid; i < 128 * K / 4; i += 256) {
            int row = i / (K / 4), c4 = (i % (K / 4)) * 4;
            float4 v = *(float4*)&stage[i * 4];
            uint2 hi, lo;
            split4(v, hi, lo);
            *(uint2*)&Ahi[row * SA + c4] = hi;
            *(uint2*)&Alo[row * SA + c4] = lo;
        }
        __syncthreads();
        if (ti + (int)gridDim.x < ntiles) {
            const float* Xt = X + (size_t)(ti + gridDim.x) * 128 * K;
            for (int i = tid; i < 128 * K / 4; i += 256)
                cp_async16(stage + i * 4, Xt + i * 4);
            asm volatile("cp.async.commit_group;" ::: "memory");
        }

        float c[2][8][4];
#pragma unroll
        for (int i = 0; i < 2; i++)
#pragma unroll
            for (int j = 0; j < 8; j++)
#pragma unroll
                for (int q = 0; q < 4; q++) c[i][j][q] = 0.0f;

#pragma unroll
        for (int kc = 0; kc < K / 16; kc++) {
            uint32_t Bh[4][4], Bl[4][4];
#pragma unroll
            for (int jp = 0; jp < 4; jp++) {
                int base = (wn * 64 + jp * 16 + qrow) * SA + kc * 16 + qk;
                Bh[jp][0] = *(const uint32_t*)&Bhi[base];
                Bh[jp][1] = *(const uint32_t*)&Bhi[base + 8];
                Bh[jp][2] = *(const uint32_t*)&Bhi[base + 8 * SA];
                Bh[jp][3] = *(const uint32_t*)&Bhi[base + 8 * SA + 8];
                Bl[jp][0] = *(const uint32_t*)&Blo[base];
                Bl[jp][1] = *(const uint32_t*)&Blo[base + 8];
                Bl[jp][2] = *(const uint32_t*)&Blo[base + 8 * SA];
                Bl[jp][3] = *(const uint32_t*)&Blo[base + 8 * SA + 8];
            }
#pragma unroll
            for (int ib = 0; ib < 2; ib++) {
                int base = (wm * 32 + ib * 16 + qrow) * SA + kc * 16 + qk;
                uint32_t Ah[4], Al[4];
                Ah[0] = *(const uint32_t*)&Ahi[base];
                Ah[1] = *(const uint32_t*)&Ahi[base + 8 * SA];
                Ah[2] = *(const uint32_t*)&Ahi[base + 8];
                Ah[3] = *(const uint32_t*)&Ahi[base + 8 * SA + 8];
                Al[0] = *(const uint32_t*)&Alo[base];
                Al[1] = *(const uint32_t*)&Alo[base + 8 * SA];
                Al[2] = *(const uint32_t*)&Alo[base + 8];
                Al[3] = *(const uint32_t*)&Alo[base + 8 * SA + 8];
#pragma unroll
                for (int jp = 0; jp < 4; jp++)
#pragma unroll
                    for (int h = 0; h < 2; h++) {
                        float* cc = c[ib][jp * 2 + h];
                        mma_bf16(cc, Ah, &Bh[jp][h * 2]);
                        mma_bf16(cc, Ah, &Bl[jp][h * 2]);
                        mma_bf16(cc, Al, &Bh[jp][h * 2]);
                    }
            }
        }

        const size_t token0 = (size_t)ti * 128;
#pragma unroll
        for (int ib = 0; ib < 2; ib++) {
            size_t row = token0 + wm * 32 + ib * 16 + qrow;
#pragma unroll
            for (int j = 0; j < 8; j++) {
                int col = wn * 64 + j * 8 + qk;
                float b0 = bsum[col], b1 = bsum[col + 1];
                *(float2*)&gxo[row * 256 + col] =
                    make_float2(c[ib][j][0] + b0, c[ib][j][1] + b1);
                *(float2*)&gxo[(row + 8) * 256 + col] =
                    make_float2(c[ib][j][2] + b0, c[ib][j][3] + b1);
            }
        }
        __syncthreads();
    }
}

// ---------------- mma recurrence: gates_t = gx_t + h @ Whh'^T ----------------
// Double-buffered h state (one __syncthreads per step), direct scattered output
// stores (no smem staging). Whh fragments hoisted into registers.
template <bool VERT, int T, int STOT, int NSEQ, int OT, int SDIV, int OHI>
__global__ void __launch_bounds__(256, 1)
lstm_recur_mma(const float* __restrict__ WhhF, const float* __restrict__ WhhB) {
    constexpr int MT = NSEQ / 16;
    constexpr int SW = 72;
    extern __shared__ char smraw[];
    uint16_t* WHi = (uint16_t*)smraw;            // 256*SW (weight staging, transient)
    uint16_t* WLo = WHi + 256 * SW;
    // h state double buffers (aliased over weight staging after hoist)
    uint16_t* hHi0 = (uint16_t*)smraw;
    uint16_t* hLo0 = hHi0 + NSEQ * SW;
    uint16_t* hHi1 = hLo0 + NSEQ * SW;
    uint16_t* hLo1 = hHi1 + NSEQ * SW;

    const int tid = threadIdx.x;
    const int wn = tid >> 5;
    const int lane = tid & 31;
    const int qrow = lane >> 2;
    const int qk = (lane & 3) * 2;
    const int par = lane & 1;
    const int dir = blockIdx.y;
    const int s0 = blockIdx.x * NSEQ;

    const float* Whh = dir ? WhhB : WhhF;
    const float* gxd = g_gx + (size_t)dir * ((size_t)262144 * 256);
    float* outbuf = VERT ? g_vout : g_vbuf;

    // stage permuted Whh hi/lo
    for (int i = tid; i < 256 * 16; i += 256) {
        int rr = i >> 4, c16 = i & 15;
        int src = (rr & 3) * 64 + (rr >> 2);
        float4 v = ((const float4*)Whh)[src * 16 + c16];
        uint2 hi, lo;
        split4(v, hi, lo);
        *(uint2*)&WHi[rr * SW + c16 * 4] = hi;
        *(uint2*)&WLo[rr * SW + c16 * 4] = lo;
    }
    __syncthreads();

    uint32_t Bh[2][4][4], Bl[2][4][4];
#pragma unroll
    for (int jp = 0; jp < 2; jp++)
#pragma unroll
        for (int kc = 0; kc < 4; kc++) {
            int base = (wn * 32 + jp * 16 + qrow) * SW + kc * 16 + qk;
            Bh[jp][kc][0] = *(const uint32_t*)&WHi[base];
            Bh[jp][kc][1] = *(const uint32_t*)&WHi[base + 8];
            Bh[jp][kc][2] = *(const uint32_t*)&WHi[base + 8 * SW];
            Bh[jp][kc][3] = *(const uint32_t*)&WHi[base + 8 * SW + 8];
            Bl[jp][kc][0] = *(const uint32_t*)&WLo[base];
            Bl[jp][kc][1] = *(const uint32_t*)&WLo[base + 8];
            Bl[jp][kc][2] = *(const uint32_t*)&WLo[base + 8 * SW];
            Bl[jp][kc][3] = *(const uint32_t*)&WLo[base + 8 * SW + 8];
        }
    __syncthreads();   // done reading staging; alias as h buffers

    for (int i = tid; i < NSEQ * SW; i += 256) { hHi0[i] = 0; hLo0[i] = 0; }

    float cur[MT][2][2][4];
    {
        int tt0 = dir ? (T - 1) : 0;
#pragma unroll
        for (int mt = 0; mt < MT; mt++)
#pragma unroll
            for (int jp = 0; jp < 2; jp++)
#pragma unroll
                for (int h8 = 0; h8 < 2; h8++) {
                    const float* p = gxd +
                        ((size_t)tt0 * STOT + s0 + mt * 16 + qrow) * 256 +
                        (wn * 32 + jp * 16 + h8 * 8 + qk);
                    float2 ab = *(const float2*)p;
                    float2 cd = *(const float2*)(p + 8 * 256);
                    cur[mt][jp][h8][0] = ab.x; cur[mt][jp][h8][1] = ab.y;
                    cur[mt][jp][h8][2] = cd.x; cur[mt][jp][h8][3] = cd.y;
                }
    }
    __syncthreads();

    float creg[MT][2][2];
#pragma unroll
    for (int mt = 0; mt < MT; mt++)
#pragma unroll
        for (int jp = 0; jp < 2; jp++)
#pragma unroll
            for (int h8 = 0; h8 < 2; h8++) creg[mt][jp][h8] = 0.0f;

    for (int t = 0; t < T; t++) {
        const int tt = dir ? (T - 1 - t) : t;
        const bool havepre = (t + 1 < T);
        const uint16_t* rHi = (t & 1) ? hHi1 : hHi0;
        const uint16_t* rLo = (t & 1) ? hLo1 : hLo0;
        uint16_t* wHi = (t & 1) ? hHi0 : hHi1;
        uint16_t* wLo = (t & 1) ? hLo0 : hLo1;

        float nxt[MT][2][2][4];
        if (havepre) {
            int tn = dir ? (tt - 1) : (tt + 1);
#pragma unroll
            for (int mt = 0; mt < MT; mt++)
#pragma unroll
                for (int jp = 0; jp < 2; jp++)
#pragma unroll
                    for (int h8 = 0; h8 < 2; h8++) {
                        const float* p = gxd +
                            ((size_t)tn * STOT + s0 + mt * 16 + qrow) * 256 +
                            (wn * 32 + jp * 16 + h8 * 8 + qk);
                        float2 ab = *(const float2*)p;
                        float2 cd = *(const float2*)(p + 8 * 256);
                        nxt[mt][jp][h8][0] = ab.x; nxt[mt][jp][h8][1] = ab.y;
                        nxt[mt][jp][h8][2] = cd.x; nxt[mt][jp][h8][3] = cd.y;
                    }
        }

#pragma unroll
        for (int kc = 0; kc < 4; kc++) {
            uint32_t Ah[MT][4], Al[MT][4];
#pragma unroll
            for (int mt = 0; mt < MT; mt++) {
                int base = (mt * 16 + qrow) * SW + kc * 16 + qk;
                Ah[mt][0] = *(const uint32_t*)&rHi[base];
                Ah[mt][1] = *(const uint32_t*)&rHi[base + 8 * SW];
                Ah[mt][2] = *(const uint32_t*)&rHi[base + 8];
                Ah[mt][3] = *(const uint32_t*)&rHi[base + 8 * SW + 8];
                Al[mt][0] = *(const uint32_t*)&rLo[base];
                Al[mt][1] = *(const uint32_t*)&rLo[base + 8 * SW];
                Al[mt][2] = *(const uint32_t*)&rLo[base + 8];
                Al[mt][3] = *(const uint32_t*)&rLo[base + 8 * SW + 8];
            }
#pragma unroll
            for (int mt = 0; mt < MT; mt++)
#pragma unroll
                for (int jp = 0; jp < 2; jp++)
#pragma unroll
                    for (int h8 = 0; h8 < 2; h8++) {
                        float* cc = cur[mt][jp][h8];
                        mma_bf16(cc, Ah[mt], &Bh[jp][kc][h8 * 2]);
                        mma_bf16(cc, Ah[mt], &Bl[jp][kc][h8 * 2]);
                        mma_bf16(cc, Al[mt], &Bh[jp][kc][h8 * 2]);
                    }
        }

        // gate exchange + activations + direct stores
#pragma unroll
        for (int mt = 0; mt < MT; mt++)
#pragma unroll
            for (int jp = 0; jp < 2; jp++)
#pragma unroll
                for (int h8 = 0; h8 < 2; h8++) {
                    float* cc = cur[mt][jp][h8];
                    float s0v = par ? cc[0] : cc[2];
                    float s1v = par ? cc[1] : cc[3];
                    float r0 = __shfl_xor_sync(0xFFFFFFFFu, s0v, 1);
                    float r1 = __shfl_xor_sync(0xFFFFFFFFu, s1v, 1);
                    float iv, fv, gv, ov;
                    if (!par) { iv = cc[0]; fv = cc[1]; gv = r0; ov = r1; }
                    else      { iv = r0;    fv = r1;    gv = cc[2]; ov = cc[3]; }
                    float cst = sigm(fv) * creg[mt][jp][h8] + sigm(iv) * tanh_fast(gv);
                    creg[mt][jp][h8] = cst;
                    float hv = sigm(ov) * tanh_fast(cst);

                    int j = wn * 8 + jp * 4 + h8 * 2 + (qk >> 2);
                    int myrow = mt * 16 + qrow + par * 8;
                    uint16_t hb, lb;
                    split1(hv, hb, lb);
                    wHi[myrow * SW + j] = hb;
                    wLo[myrow * SW + j] = lb;
                    int s = s0 + myrow;
                    size_t addr = (size_t)(s / SDIV) * OHI + (size_t)(s % SDIV) * 128 +
                                  (size_t)tt * OT + (size_t)dir * 64 + j;
                    outbuf[addr] = hv;
                }

        if (havepre) {
#pragma unroll
            for (int mt = 0; mt < MT; mt++)
#pragma unroll
                for (int jp = 0; jp < 2; jp++)
#pragma unroll
                    for (int h8 = 0; h8 < 2; h8++)
#pragma unroll
                        for (int q = 0; q < 4; q++)
                            cur[mt][jp][h8][q] = nxt[mt][jp][h8][q];
        }
        __syncthreads();   // h write-buffer visible for next step's reads
    }
}

// ---------------- launch ----------------
extern "C" void kernel_launch(void* const* d_in, const int* in_sizes, int n_in,
                              void* d_out, int out_size) {
    const float* img    = (const float*)d_in[0];
    const float* hWihF  = (const float*)d_in[1];
    const float* hWhhF  = (const float*)d_in[2];
    const float* hbihF  = (const float*)d_in[3];
    const float* hbhhF  = (const float*)d_in[4];
    const float* hWihB  = (const float*)d_in[5];
    const float* hWhhB  = (const float*)d_in[6];
    const float* hbihB  = (const float*)d_in[7];
    const float* hbhhB  = (const float*)d_in[8];
    const float* vWihF  = (const float*)d_in[9];
    const float* vWhhF  = (const float*)d_in[10];
    const float* vbihF  = (const float*)d_in[11];
    const float* vbhhF  = (const float*)d_in[12];
    const float* vWihB  = (const float*)d_in[13];
    const float* vWhhB  = (const float*)d_in[14];
    const float* vbihB  = (const float*)d_in[15];
    const float* vbhhB  = (const float*)d_in[16];
    float* out = (float*)d_out;

    auto hG = gx_gemm<64, false>;
    auto vG = gx_gemm<128, true>;
    auto hR = lstm_recur_mma<false, 256, 1024, 16, 1024, 8, 262144>;
    auto vR = lstm_recur_mma<true, 128, 2048, 32, 262144, (1 << 28), 0>;

    const int smemHG = 128 * 64 * 4 + 4 * 128 * (64 + 8) * 2 + 512;    // 107,008 B
    const int smemVG = 128 * 128 * 4 + 4 * 128 * (128 + 8) * 2 + 512;  // 205,312 B
    const int smemR = 2 * 256 * 72 * 2;                                //  73,728 B
    cudaFuncSetAttribute(hG, cudaFuncAttributeMaxDynamicSharedMemorySize, smemHG);
    cudaFuncSetAttribute(vG, cudaFuncAttributeMaxDynamicSharedMemorySize, smemVG);
    cudaFuncSetAttribute(hR, cudaFuncAttributeMaxDynamicSharedMemorySize, smemR);
    cudaFuncSetAttribute(vR, cudaFuncAttributeMaxDynamicSharedMemorySize, smemR);

    // 1) img -> g_xh
    transpose_in_k<<<dim3(WW / 32, DD / 32, HH * BB), dim3(32, 8)>>>(img);

    // 2) gxh (permuted, bias folded)
    hG<<<dim3(37, 4), 256, smemHG>>>(hWihF, hWihB, hbihF, hbhhF, hbihB, hbhhB, 2048);

    // 3) capture-alignment probe (makes hR launch #4 for ncu)
    probe_k<<<1, 32>>>();

    // 4) horizontal mma recurrence -> g_vbuf
    hR<<<dim3(64, 2), 256, smemR>>>(hWhhF, hWhhB);

    // 5) gxv
    vG<<<dim3(37, 4), 256, smemVG>>>(vWihF, vWihB, vbihF, vbhhF, vbihB, vbhhB, 2048);

    // 6) vertical mma recurrence -> g_vout
    vR<<<dim3(64, 2), 256, smemR>>>(vWhhF, vWhhB);

    // 7) g_vout -> out
    transpose_out_k<<<dim3(WW / 32, 128 / 32, HH * BB), dim3(32, 8)>>>(out);
}

// round 11
// speedup vs baseline: 2.2376x; 1.2834x over previous
#include <cuda_runtime.h>
#include <cuda_bf16.h>
#include <math.h>
#include <stdint.h>

#define BB 8
#define DD 64
#define HH 128
#define WW 256

// ---------------- scratch (static device globals) ----------------
// ONLY referenced from device code (host-side symbol use = host shadow under ATS!)
__device__ float g_xh[(size_t)WW * HH * BB * DD];       // [w][h*8+b][64]
__device__ float g_vbuf[(size_t)HH * WW * BB * 128];    // [h][w*8+b][128]
__device__ float g_vout[(size_t)HH * WW * BB * 128];    // [h][w*8+b][128]
__device__ float g_gx[(size_t)2 * 262144 * 256];        // [dir][token][perm gate 4j+g], bias folded

__device__ __forceinline__ uint32_t smem_u32(const void* p) {
    uint32_t a;
    asm("{ .reg .u64 t; cvta.to.shared.u64 t, %1; cvt.u32.u64 %0, t; }" : "=r"(a) : "l"(p));
    return a;
}

__device__ __forceinline__ void cp_async16(void* dst, const void* src) {
    asm volatile("cp.async.cg.shared.global [%0], [%1], 16;"
                 :: "r"(smem_u32(dst)), "l"(src) : "memory");
}

__device__ __forceinline__ void mma_bf16(float* c, const uint32_t* a, const uint32_t* b) {
    asm volatile(
        "mma.sync.aligned.m16n8k16.row.col.f32.bf16.bf16.f32 "
        "{%0,%1,%2,%3}, {%4,%5,%6,%7}, {%8,%9}, {%0,%1,%2,%3};"
        : "+f"(c[0]), "+f"(c[1]), "+f"(c[2]), "+f"(c[3])
        : "r"(a[0]), "r"(a[1]), "r"(a[2]), "r"(a[3]), "r"(b[0]), "r"(b[1]));
}

__device__ __forceinline__ uint32_t pack_bf16x2(float a, float b) {
    uint32_t r;
    asm("{ .reg .b16 lo, hi;\n\t"
        "cvt.rn.bf16.f32 lo, %1;\n\t"
        "cvt.rn.bf16.f32 hi, %2;\n\t"
        "mov.b32 %0, {lo, hi}; }"
        : "=r"(r) : "f"(a), "f"(b));
    return r;
}

// hi = truncated-bf16 (integer bit ops), lo = rn-bf16 of exact residual
__device__ __forceinline__ void split4(float4 v, uint2& hi, uint2& lo) {
    uint32_t ux = __float_as_uint(v.x), uy = __float_as_uint(v.y);
    uint32_t uz = __float_as_uint(v.z), uw = __float_as_uint(v.w);
    hi.x = (ux >> 16) | (uy & 0xFFFF0000u);
    hi.y = (uz >> 16) | (uw & 0xFFFF0000u);
    float lx = v.x - __uint_as_float(ux & 0xFFFF0000u);
    float ly = v.y - __uint_as_float(uy & 0xFFFF0000u);
    float lz = v.z - __uint_as_float(uz & 0xFFFF0000u);
    float lw = v.w - __uint_as_float(uw & 0xFFFF0000u);
    lo.x = pack_bf16x2(lx, ly);
    lo.y = pack_bf16x2(lz, lw);
}

__device__ __forceinline__ void split1(float x, uint16_t& h, uint16_t& l) {
    uint32_t u = __float_as_uint(x);
    h = (uint16_t)(u >> 16);
    float r = x - __uint_as_float(u & 0xFFFF0000u);
    uint16_t lb;
    asm("cvt.rn.bf16.f32 %0, %1;" : "=h"(lb) : "f"(r));
    l = lb;
}

// capture-alignment probe: keeps ncu -c 1 on the hR launch (#4). Does nothing.
__global__ void probe_k() {}

// ---------------- transposes ----------------
__global__ void transpose_in_k(const float* __restrict__ img) {
    __shared__ float tile[32][33];
    const int tx = threadIdx.x, ty = threadIdx.y;
    const int b = blockIdx.z & 7, h = blockIdx.z >> 3;
    const int w0 = blockIdx.x * 32, d0 = blockIdx.y * 32;
#pragma unroll
    for (int i = 0; i < 32; i += 8) {
        int d = d0 + ty + i;
        tile[ty + i][tx] = img[(((size_t)b * DD + d) * HH + h) * WW + w0 + tx];
    }
    __syncthreads();
#pragma unroll
    for (int i = 0; i < 32; i += 8) {
        int w = w0 + ty + i;
        g_xh[((size_t)w * (HH * BB) + blockIdx.z) * DD + d0 + tx] = tile[tx][ty + i];
    }
}

__global__ void transpose_out_k(float* __restrict__ out) {
    __shared__ float tile[32][33];
    const int tx = threadIdx.x, ty = threadIdx.y;
    const int b = blockIdx.z & 7, h = blockIdx.z >> 3;
    const int w0 = blockIdx.x * 32, c0 = blockIdx.y * 32;
#pragma unroll
    for (int i = 0; i < 32; i += 8) {
        int w = w0 + ty + i;
        tile[ty + i][tx] =
            g_vout[(size_t)h * (WW * BB * 128) + ((size_t)w * BB + b) * 128 + c0 + tx];
    }
    __syncthreads();
#pragma unroll
    for (int i = 0; i < 32; i += 8) {
        int c = c0 + ty + i;
        out[(((size_t)b * 128 + c) * HH + h) * WW + w0 + tx] = tile[tx][ty + i];
    }
}

// ---------------- gx GEMM: gx[dir][token][perm 4j+g] = X @ Wih^T + bias ----------------
template <int K, bool VERT>
__global__ void __launch_bounds__(256, 1)
gx_gemm(const float* __restrict__ WF, const float* __restrict__ WB,
        const float* __restrict__ bihF, const float* __restrict__ bhhF,
        const float* __restrict__ bihB, const float* __restrict__ bhhB, int ntiles) {
    constexpr int SA = K + 8;
    extern __shared__ float smf[];
    float* stage = smf;                               // 128*K fp32
    uint16_t* Ahi = (uint16_t*)(stage + 128 * K);     // 128*SA each
    uint16_t* Alo = Ahi + 128 * SA;
    uint16_t* Bhi = Alo + 128 * SA;
    uint16_t* Blo = Bhi + 128 * SA;
    float* bsum = (float*)(Blo + 128 * SA);           // 128

    const float* X = VERT ? g_vbuf : g_xh;

    const int tid = threadIdx.x;
    const int warp = tid >> 5;
    const int lane = tid & 31;
    const int wm = warp & 3;
    const int wn = warp >> 2;
    const int half = blockIdx.y & 1;
    const int dir = blockIdx.y >> 1;

    const float* W = dir ? WB : WF;
    const float* bih = dir ? bihB : bihF;
    const float* bhh = dir ? bhhB : bhhF;
    float* gxo = g_gx + (size_t)dir * ((size_t)262144 * 256) + half * 128;

    for (int i = tid; i < 128 * (K / 4); i += 256) {
        int rr = i / (K / 4), c16 = i % (K / 4);
        int src = (rr & 3) * 64 + 32 * half + (rr >> 2);
        float4 v = ((const float4*)W)[src * (K / 4) + c16];
        uint2 hi, lo;
        split4(v, hi, lo);
        *(uint2*)&Bhi[rr * SA + c16 * 4] = hi;
        *(uint2*)&Blo[rr * SA + c16 * 4] = lo;
    }
    if (tid < 128) {
        int G = (tid & 3) * 64 + 32 * half + (tid >> 2);
        bsum[tid] = bih[G] + bhh[G];
    }

    const int qrow = lane >> 2;
    const int qk = (lane & 3) * 2;

    int ti = blockIdx.x;
    {
        const float* Xt = X + (size_t)ti * 128 * K;
        for (int i = tid; i < 128 * K / 4; i += 256)
            cp_async16(stage + i * 4, Xt + i * 4);
        asm volatile("cp.async.commit_group;" ::: "memory");
    }

    for (; ti < ntiles; ti += gridDim.x) {
        asm volatile("cp.async.wait_group 0;" ::: "memory");
        __syncthreads();
        for (int i = tid; i < 128 * K / 4; i += 256) {
            int row = i / (K / 4), c4 = (i % (K / 4)) * 4;
            float4 v = *(float4*)&stage[i * 4];
            uint2 hi, lo;
            split4(v, hi, lo);
            *(uint2*)&Ahi[row * SA + c4] = hi;
            *(uint2*)&Alo[row * SA + c4] = lo;
        }
        __syncthreads();
        if (ti + (int)gridDim.x < ntiles) {
            const float* Xt = X + (size_t)(ti + gridDim.x) * 128 * K;
            for (int i = tid; i < 128 * K / 4; i += 256)
                cp_async16(stage + i * 4, Xt + i * 4);
            asm volatile("cp.async.commit_group;" ::: "memory");
        }

        float c[2][8][4];
#pragma unroll
        for (int i = 0; i < 2; i++)
#pragma unroll
            for (int j = 0; j < 8; j++)
#pragma unroll
                for (int q = 0; q < 4; q++) c[i][j][q] = 0.0f;

#pragma unroll
        for (int kc = 0; kc < K / 16; kc++) {
            uint32_t Bh[4][4], Bl[4][4];
#pragma unroll
            for (int jp = 0; jp < 4; jp++) {
                int base = (wn * 64 + jp * 16 + qrow) * SA + kc * 16 + qk;
                Bh[jp][0] = *(const uint32_t*)&Bhi[base];
                Bh[jp][1] = *(const uint32_t*)&Bhi[base + 8];
                Bh[jp][2] = *(const uint32_t*)&Bhi[base + 8 * SA];
                Bh[jp][3] = *(const uint32_t*)&Bhi[base + 8 * SA + 8];
                Bl[jp][0] = *(const uint32_t*)&Blo[base];
                Bl[jp][1] = *(const uint32_t*)&Blo[base + 8];
                Bl[jp][2] = *(const uint32_t*)&Blo[base + 8 * SA];
                Bl[jp][3] = *(const uint32_t*)&Blo[base + 8 * SA + 8];
            }
#pragma unroll
            for (int ib = 0; ib < 2; ib++) {
                int base = (wm * 32 + ib * 16 + qrow) * SA + kc * 16 + qk;
                uint32_t Ah[4], Al[4];
                Ah[0] = *(const uint32_t*)&Ahi[base];
                Ah[1] = *(const uint32_t*)&Ahi[base + 8 * SA];
                Ah[2] = *(const uint32_t*)&Ahi[base + 8];
                Ah[3] = *(const uint32_t*)&Ahi[base + 8 * SA + 8];
                Al[0] = *(const uint32_t*)&Alo[base];
                Al[1] = *(const uint32_t*)&Alo[base + 8 * SA];
                Al[2] = *(const uint32_t*)&Alo[base + 8];
                Al[3] = *(const uint32_t*)&Alo[base + 8 * SA + 8];
#pragma unroll
                for (int jp = 0; jp < 4; jp++)
#pragma unroll
                    for (int h = 0; h < 2; h++) {
                        float* cc = c[ib][jp * 2 + h];
                        mma_bf16(cc, Ah, &Bh[jp][h * 2]);
                        mma_bf16(cc, Ah, &Bl[jp][h * 2]);
                        mma_bf16(cc, Al, &Bh[jp][h * 2]);
                    }
            }
        }

        const size_t token0 = (size_t)ti * 128;
#pragma unroll
        for (int ib = 0; ib < 2; ib++) {
            size_t row = token0 + wm * 32 + ib * 16 + qrow;
#pragma unroll
            for (int j = 0; j < 8; j++) {
                int col = wn * 64 + j * 8 + qk;
                float b0 = bsum[col], b1 = bsum[col + 1];
                *(float2*)&gxo[row * 256 + col] =
                    make_float2(c[ib][j][0] + b0, c[ib][j][1] + b1);
                *(float2*)&gxo[(row + 8) * 256 + col] =
                    make_float2(c[ib][j][2] + b0, c[ib][j][3] + b1);
            }
        }
        __syncthreads();
    }
}

// ---------------- mma recurrence: gates_t = gx_t + h @ Whh'^T ----------------
// Lean step: running pointers (no per-step addr math), unroll-2 register role
// swap (no cur=nxt copy), fast-division activations, split accumulators (MT=1).
template <bool VERT, int T, int STOT, int NSEQ, int OT, int SDIV, int OHI>
__global__ void __launch_bounds__(256, 1)
lstm_recur_mma(const float* __restrict__ WhhF, const float* __restrict__ WhhB) {
    constexpr int MT = NSEQ / 16;
    constexpr bool SACC = (MT == 1);
    constexpr int SW = 72;
    constexpr int NG = MT * 4;
    extern __shared__ char smraw[];
    uint16_t* WHi = (uint16_t*)smraw;            // weight staging (transient)
    uint16_t* WLo = WHi + 256 * SW;
    uint16_t* hHi0 = (uint16_t*)smraw;           // h double buffers (alias staging)
    uint16_t* hLo0 = hHi0 + NSEQ * SW;
    uint16_t* hHi1 = hLo0 + NSEQ * SW;
    uint16_t* hLo1 = hHi1 + NSEQ * SW;

    const int tid = threadIdx.x;
    const int wn = tid >> 5;
    const int lane = tid & 31;
    const int qrow = lane >> 2;
    const int qk = (lane & 3) * 2;
    const int par = lane & 1;
    const int dir = blockIdx.y;
    const int s0 = blockIdx.x * NSEQ;

    const float* Whh = dir ? WhhB : WhhF;
    const float* gxd = g_gx + (size_t)dir * ((size_t)262144 * 256);
    float* outbuf = VERT ? g_vout : g_vbuf;

    // stage permuted Whh hi/lo
    for (int i = tid; i < 256 * 16; i += 256) {
        int rr = i >> 4, c16 = i & 15;
        int src = (rr & 3) * 64 + (rr >> 2);
        float4 v = ((const float4*)Whh)[src * 16 + c16];
        uint2 hi, lo;
        split4(v, hi, lo);
        *(uint2*)&WHi[rr * SW + c16 * 4] = hi;
        *(uint2*)&WLo[rr * SW + c16 * 4] = lo;
    }
    __syncthreads();

    uint32_t Bh[2][4][4], Bl[2][4][4];
#pragma unroll
    for (int jp = 0; jp < 2; jp++)
#pragma unroll
        for (int kc = 0; kc < 4; kc++) {
            int base = (wn * 32 + jp * 16 + qrow) * SW + kc * 16 + qk;
            Bh[jp][kc][0] = *(const uint32_t*)&WHi[base];
            Bh[jp][kc][1] = *(const uint32_t*)&WHi[base + 8];
            Bh[jp][kc][2] = *(const uint32_t*)&WHi[base + 8 * SW];
            Bh[jp][kc][3] = *(const uint32_t*)&WHi[base + 8 * SW + 8];
            Bl[jp][kc][0] = *(const uint32_t*)&WLo[base];
            Bl[jp][kc][1] = *(const uint32_t*)&WLo[base + 8];
            Bl[jp][kc][2] = *(const uint32_t*)&WLo[base + 8 * SW];
            Bl[jp][kc][3] = *(const uint32_t*)&WLo[base + 8 * SW + 8];
        }
    __syncthreads();   // done reading staging; alias as h buffers

    for (int i = tid; i < NSEQ * SW; i += 256) { hHi0[i] = 0; hLo0[i] = 0; }

    // running pointers + precomputed per-group offsets
    const int tt0 = dir ? (T - 1) : 0;
    const int dstep = dir ? -(STOT * 256) : (STOT * 256);
    const float* gp = gxd + ((size_t)tt0 * STOT + s0 + qrow) * 256 + wn * 32 + qk;
    const int dOT = dir ? -OT : OT;
    float* op = outbuf + (size_t)tt0 * OT + (size_t)dir * 64;
    int ooff[NG], hwoff[NG];
#pragma unroll
    for (int mt = 0; mt < MT; mt++)
#pragma unroll
        for (int jp = 0; jp < 2; jp++)
#pragma unroll
            for (int h8 = 0; h8 < 2; h8++) {
                int g = mt * 4 + jp * 2 + h8;
                int j = wn * 8 + jp * 4 + h8 * 2 + (qk >> 2);
                int myrow = mt * 16 + qrow + par * 8;
                int s = s0 + myrow;
                ooff[g] = (s / SDIV) * OHI + (s % SDIV) * 128 + j;
                hwoff[g] = myrow * SW + j;
            }
    const int abase = qrow * SW + qk;

    float cur[MT][2][2][4], nxt[MT][2][2][4];
#pragma unroll
    for (int mt = 0; mt < MT; mt++)
#pragma unroll
        for (int jp = 0; jp < 2; jp++)
#pragma unroll
            for (int h8 = 0; h8 < 2; h8++) {
                const float* p = gp + mt * (16 * 256) + jp * 16 + h8 * 8;
                float2 ab = *(const float2*)p;
                float2 cd = *(const float2*)(p + 8 * 256);
                cur[mt][jp][h8][0] = ab.x; cur[mt][jp][h8][1] = ab.y;
                cur[mt][jp][h8][2] = cd.x; cur[mt][jp][h8][3] = cd.y;
            }
    gp += dstep;

    float creg[MT][2][2];
#pragma unroll
    for (int mt = 0; mt < MT; mt++)
#pragma unroll
        for (int jp = 0; jp < 2; jp++)
#pragma unroll
            for (int h8 = 0; h8 < 2; h8++) creg[mt][jp][h8] = 0.0f;
    __syncthreads();

#define LSTM_STEP(RHI, RLO, WHI_, WLO_, CUR, NXT, TQ)                            \
    do {                                                                         \
        if ((TQ) + 1 < T) {                                                      \
            _Pragma("unroll") for (int mt = 0; mt < MT; mt++)                    \
            _Pragma("unroll") for (int jp = 0; jp < 2; jp++)                     \
            _Pragma("unroll") for (int h8 = 0; h8 < 2; h8++) {                   \
                const float* p = gp + mt * (16 * 256) + jp * 16 + h8 * 8;        \
                float2 ab = *(const float2*)p;                                   \
                float2 cd = *(const float2*)(p + 8 * 256);                       \
                NXT[mt][jp][h8][0] = ab.x; NXT[mt][jp][h8][1] = ab.y;            \
                NXT[mt][jp][h8][2] = cd.x; NXT[mt][jp][h8][3] = cd.y;            \
            }                                                                    \
        }                                                                        \
        float accB[MT][2][2][4];                                                 \
        if (SACC) {                                                              \
            _Pragma("unroll") for (int mt = 0; mt < MT; mt++)                    \
            _Pragma("unroll") for (int jp = 0; jp < 2; jp++)                     \
            _Pragma("unroll") for (int h8 = 0; h8 < 2; h8++)                     \
            _Pragma("unroll") for (int q = 0; q < 4; q++)                        \
                accB[mt][jp][h8][q] = 0.0f;                                      \
        }                                                                        \
        _Pragma("unroll") for (int kc = 0; kc < 4; kc++) {                       \
            uint32_t Ah[MT][4], Al[MT][4];                                       \
            _Pragma("unroll") for (int mt = 0; mt < MT; mt++) {                  \
                int base = abase + mt * 16 * SW + kc * 16;                       \
                Ah[mt][0] = *(const uint32_t*)&RHI[base];                        \
                Ah[mt][1] = *(const uint32_t*)&RHI[base + 8 * SW];               \
                Ah[mt][2] = *(const uint32_t*)&RHI[base + 8];                    \
                Ah[mt][3] = *(const uint32_t*)&RHI[base + 8 * SW + 8];           \
                Al[mt][0] = *(const uint32_t*)&RLO[base];                        \
                Al[mt][1] = *(const uint32_t*)&RLO[base + 8 * SW];               \
                Al[mt][2] = *(const uint32_t*)&RLO[base + 8];                    \
                Al[mt][3] = *(const uint32_t*)&RLO[base + 8 * SW + 8];           \
            }                                                                    \
            _Pragma("unroll") for (int mt = 0; mt < MT; mt++)                    \
            _Pragma("unroll") for (int jp = 0; jp < 2; jp++)                     \
            _Pragma("unroll") for (int h8 = 0; h8 < 2; h8++) {                   \
                mma_bf16(CUR[mt][jp][h8], Ah[mt], &Bh[jp][kc][h8 * 2]);          \
                float* tb = SACC ? accB[mt][jp][h8] : CUR[mt][jp][h8];           \
                mma_bf16(tb, Ah[mt], &Bl[jp][kc][h8 * 2]);                       \
                mma_bf16(tb, Al[mt], &Bh[jp][kc][h8 * 2]);                       \
            }                                                                    \
        }                                                                        \
        _Pragma("unroll") for (int mt = 0; mt < MT; mt++)                        \
        _Pragma("unroll") for (int jp = 0; jp < 2; jp++)                         \
        _Pragma("unroll") for (int h8 = 0; h8 < 2; h8++) {                       \
            int g = mt * 4 + jp * 2 + h8;                                        \
            float cc0 = CUR[mt][jp][h8][0], cc1 = CUR[mt][jp][h8][1];            \
            float cc2 = CUR[mt][jp][h8][2], cc3 = CUR[mt][jp][h8][3];            \
            if (SACC) {                                                          \
                cc0 += accB[mt][jp][h8][0]; cc1 += accB[mt][jp][h8][1];          \
                cc2 += accB[mt][jp][h8][2]; cc3 += accB[mt][jp][h8][3];          \
            }                                                                    \
            float s0v = par ? cc0 : cc2;                                         \
            float s1v = par ? cc1 : cc3;                                         \
            float r0 = __shfl_xor_sync(0xFFFFFFFFu, s0v, 1);                     \
            float r1 = __shfl_xor_sync(0xFFFFFFFFu, s1v, 1);                     \
            float iv, fv, gv, ov;                                                \
            if (!par) { iv = cc0; fv = cc1; gv = r0; ov = r1; }                  \
            else      { iv = r0;  fv = r1;  gv = cc2; ov = cc3; }                \
            float si = __fdividef(1.0f, 1.0f + __expf(-iv));                     \
            float sf = __fdividef(1.0f, 1.0f + __expf(-fv));                     \
            float so = __fdividef(1.0f, 1.0f + __expf(-ov));                     \
            float eg = __expf(2.0f * fminf(15.0f, fmaxf(-15.0f, gv)));           \
            float tg = __fdividef(eg - 1.0f, eg + 1.0f);                         \
            float cst = sf * creg[mt][jp][h8] + si * tg;                         \
            creg[mt][jp][h8] = cst;                                              \
            float ec = __expf(2.0f * fminf(15.0f, fmaxf(-15.0f, cst)));          \
            float tc = __fdividef(ec - 1.0f, ec + 1.0f);                         \
            float hv = so * tc;                                                  \
            uint16_t hb, lb;                                                     \
            split1(hv, hb, lb);                                                  \
            WHI_[hwoff[g]] = hb;                                                 \
            WLO_[hwoff[g]] = lb;                                                 \
            op[ooff[g]] = hv;                                                    \
        }                                                                        \
        gp += dstep;                                                             \
        op += dOT;                                                               \
        __syncthreads();                                                         \
    } while (0)

    for (int t = 0; t < T; t += 2) {
        LSTM_STEP(hHi0, hLo0, hHi1, hLo1, cur, nxt, t);
        LSTM_STEP(hHi1, hLo1, hHi0, hLo0, nxt, cur, t + 1);
    }
#undef LSTM_STEP
}

// ---------------- launch ----------------
extern "C" void kernel_launch(void* const* d_in, const int* in_sizes, int n_in,
                              void* d_out, int out_size) {
    const float* img    = (const float*)d_in[0];
    const float* hWihF  = (const float*)d_in[1];
    const float* hWhhF  = (const float*)d_in[2];
    const float* hbihF  = (const float*)d_in[3];
    const float* hbhhF  = (const float*)d_in[4];
    const float* hWihB  = (const float*)d_in[5];
    const float* hWhhB  = (const float*)d_in[6];
    const float* hbihB  = (const float*)d_in[7];
    const float* hbhhB  = (const float*)d_in[8];
    const float* vWihF  = (const float*)d_in[9];
    const float* vWhhF  = (const float*)d_in[10];
    const float* vbihF  = (const float*)d_in[11];
    const float* vbhhF  = (const float*)d_in[12];
    const float* vWihB  = (const float*)d_in[13];
    const float* vWhhB  = (const float*)d_in[14];
    const float* vbihB  = (const float*)d_in[15];
    const float* vbhhB  = (const float*)d_in[16];
    float* out = (float*)d_out;

    auto hG = gx_gemm<64, false>;
    auto vG = gx_gemm<128, true>;
    auto hR = lstm_recur_mma<false, 256, 1024, 16, 1024, 8, 262144>;
    auto vR = lstm_recur_mma<true, 128, 2048, 32, 262144, (1 << 28), 0>;

    const int smemHG = 128 * 64 * 4 + 4 * 128 * (64 + 8) * 2 + 512;    // 107,008 B
    const int smemVG = 128 * 128 * 4 + 4 * 128 * (128 + 8) * 2 + 512;  // 205,312 B
    const int smemR = 2 * 256 * 72 * 2;                                //  73,728 B
    cudaFuncSetAttribute(hG, cudaFuncAttributeMaxDynamicSharedMemorySize, smemHG);
    cudaFuncSetAttribute(vG, cudaFuncAttributeMaxDynamicSharedMemorySize, smemVG);
    cudaFuncSetAttribute(hR, cudaFuncAttributeMaxDynamicSharedMemorySize, smemR);
    cudaFuncSetAttribute(vR, cudaFuncAttributeMaxDynamicSharedMemorySize, smemR);

    // 1) img -> g_xh
    transpose_in_k<<<dim3(WW / 32, DD / 32, HH * BB), dim3(32, 8)>>>(img);

    // 2) gxh (permuted, bias folded)
    hG<<<dim3(37, 4), 256, smemHG>>>(hWihF, hWihB, hbihF, hbhhF, hbihB, hbhhB, 2048);

    // 3) capture-alignment probe (keeps hR at launch #4 for ncu)
    probe_k<<<1, 32>>>();

    // 4) horizontal mma recurrence -> g_vbuf
    hR<<<dim3(64, 2), 256, smemR>>>(hWhhF, hWhhB);

    // 5) gxv
    vG<<<dim3(37, 4), 256, smemVG>>>(vWihF, vWihB, vbihF, vbhhF, vbihB, vbhhB, 2048);

    // 6) vertical mma recurrence -> g_vout
    vR<<<dim3(64, 2), 256, smemR>>>(vWhhF, vWhhB);

    // 7) g_vout -> out
    transpose_out_k<<<dim3(WW / 32, 128 / 32, HH * BB), dim3(32, 8)>>>(out);
}

// round 13
// speedup vs baseline: 2.3524x; 1.0513x over previous
#include <cuda_runtime.h>
#include <cuda_bf16.h>
#include <math.h>
#include <stdint.h>

#define BB 8
#define DD 64
#define HH 128
#define WW 256

// ---------------- scratch (static device globals) ----------------
// ONLY referenced from device code (host-side symbol use = host shadow under ATS!)
__device__ float g_xh[(size_t)WW * HH * BB * DD];       // [w][h*8+b][64]
__device__ float g_vbuf[(size_t)HH * WW * BB * 128];    // [h][w*8+b][128]
__device__ float g_vout[(size_t)HH * WW * BB * 128];    // [h][w*8+b][128]
__device__ float g_gx[(size_t)2 * 262144 * 256];        // [dir][token][perm gate 4j+g], bias folded

__device__ __forceinline__ uint32_t smem_u32(const void* p) {
    uint32_t a;
    asm("{ .reg .u64 t; cvta.to.shared.u64 t, %1; cvt.u32.u64 %0, t; }" : "=r"(a) : "l"(p));
    return a;
}

__device__ __forceinline__ void cp_async16(void* dst, const void* src) {
    asm volatile("cp.async.cg.shared.global [%0], [%1], 16;"
                 :: "r"(smem_u32(dst)), "l"(src) : "memory");
}

__device__ __forceinline__ void mma_bf16(float* c, const uint32_t* a, const uint32_t* b) {
    asm volatile(
        "mma.sync.aligned.m16n8k16.row.col.f32.bf16.bf16.f32 "
        "{%0,%1,%2,%3}, {%4,%5,%6,%7}, {%8,%9}, {%0,%1,%2,%3};"
        : "+f"(c[0]), "+f"(c[1]), "+f"(c[2]), "+f"(c[3])
        : "r"(a[0]), "r"(a[1]), "r"(a[2]), "r"(a[3]), "r"(b[0]), "r"(b[1]));
}

__device__ __forceinline__ float tanh_ap(float x) {
    float y;
    asm("tanh.approx.f32 %0, %1;" : "=f"(y) : "f"(x));
    return y;
}

__device__ __forceinline__ uint32_t pack_bf16x2(float a, float b) {
    uint32_t r;
    asm("{ .reg .b16 lo, hi;\n\t"
        "cvt.rn.bf16.f32 lo, %1;\n\t"
        "cvt.rn.bf16.f32 hi, %2;\n\t"
        "mov.b32 %0, {lo, hi}; }"
        : "=r"(r) : "f"(a), "f"(b));
    return r;
}

// hi = truncated-bf16 (integer bit ops), lo = rn-bf16 of exact residual
__device__ __forceinline__ void split4(float4 v, uint2& hi, uint2& lo) {
    uint32_t ux = __float_as_uint(v.x), uy = __float_as_uint(v.y);
    uint32_t uz = __float_as_uint(v.z), uw = __float_as_uint(v.w);
    hi.x = (ux >> 16) | (uy & 0xFFFF0000u);
    hi.y = (uz >> 16) | (uw & 0xFFFF0000u);
    float lx = v.x - __uint_as_float(ux & 0xFFFF0000u);
    float ly = v.y - __uint_as_float(uy & 0xFFFF0000u);
    float lz = v.z - __uint_as_float(uz & 0xFFFF0000u);
    float lw = v.w - __uint_as_float(uw & 0xFFFF0000u);
    lo.x = pack_bf16x2(lx, ly);
    lo.y = pack_bf16x2(lz, lw);
}

__device__ __forceinline__ void split1(float x, uint16_t& h, uint16_t& l) {
    uint32_t u = __float_as_uint(x);
    h = (uint16_t)(u >> 16);
    float r = x - __uint_as_float(u & 0xFFFF0000u);
    uint16_t lb;
    asm("cvt.rn.bf16.f32 %0, %1;" : "=h"(lb) : "f"(r));
    l = lb;
}

// capture-alignment probe: keeps ncu -c 1 on the hR launch (#4). Does nothing.
__global__ void probe_k() {}

// ---------------- transposes ----------------
__global__ void transpose_in_k(const float* __restrict__ img) {
    __shared__ float tile[32][33];
    const int tx = threadIdx.x, ty = threadIdx.y;
    const int b = blockIdx.z & 7, h = blockIdx.z >> 3;
    const int w0 = blockIdx.x * 32, d0 = blockIdx.y * 32;
#pragma unroll
    for (int i = 0; i < 32; i += 8) {
        int d = d0 + ty + i;
        tile[ty + i][tx] = img[(((size_t)b * DD + d) * HH + h) * WW + w0 + tx];
    }
    __syncthreads();
#pragma unroll
    for (int i = 0; i < 32; i += 8) {
        int w = w0 + ty + i;
        g_xh[((size_t)w * (HH * BB) + blockIdx.z) * DD + d0 + tx] = tile[tx][ty + i];
    }
}

__global__ void transpose_out_k(float* __restrict__ out) {
    __shared__ float tile[32][33];
    const int tx = threadIdx.x, ty = threadIdx.y;
    const int b = blockIdx.z & 7, h = blockIdx.z >> 3;
    const int w0 = blockIdx.x * 32, c0 = blockIdx.y * 32;
#pragma unroll
    for (int i = 0; i < 32; i += 8) {
        int w = w0 + ty + i;
        tile[ty + i][tx] =
            g_vout[(size_t)h * (WW * BB * 128) + ((size_t)w * BB + b) * 128 + c0 + tx];
    }
    __syncthreads();
#pragma unroll
    for (int i = 0; i < 32; i += 8) {
        int c = c0 + ty + i;
        out[(((size_t)b * 128 + c) * HH + h) * WW + w0 + tx] = tile[tx][ty + i];
    }
}

// ---------------- gx GEMM: gx[dir][token][perm 4j+g] = X @ Wih^T + bias ----------------
template <int K, bool VERT>
__global__ void __launch_bounds__(256, 1)
gx_gemm(const float* __restrict__ WF, const float* __restrict__ WB,
        const float* __restrict__ bihF, const float* __restrict__ bhhF,
        const float* __restrict__ bihB, const float* __restrict__ bhhB, int ntiles) {
    constexpr int SA = K + 8;
    extern __shared__ float smf[];
    float* stage = smf;                               // 128*K fp32
    uint16_t* Ahi = (uint16_t*)(stage + 128 * K);     // 128*SA each
    uint16_t* Alo = Ahi + 128 * SA;
    uint16_t* Bhi = Alo + 128 * SA;
    uint16_t* Blo = Bhi + 128 * SA;
    float* bsum = (float*)(Blo + 128 * SA);           // 128

    const float* X = VERT ? g_vbuf : g_xh;

    const int tid = threadIdx.x;
    const int warp = tid >> 5;
    const int lane = tid & 31;
    const int wm = warp & 3;
    const int wn = warp >> 2;
    const int half = blockIdx.y & 1;
    const int dir = blockIdx.y >> 1;

    const float* W = dir ? WB : WF;
    const float* bih = dir ? bihB : bihF;
    const float* bhh = dir ? bhhB : bhhF;
    float* gxo = g_gx + (size_t)dir * ((size_t)262144 * 256) + half * 128;

    for (int i = tid; i < 128 * (K / 4); i += 256) {
        int rr = i / (K / 4), c16 = i % (K / 4);
        int src = (rr & 3) * 64 + 32 * half + (rr >> 2);
        float4 v = ((const float4*)W)[src * (K / 4) + c16];
        uint2 hi, lo;
        split4(v, hi, lo);
        *(uint2*)&Bhi[rr * SA + c16 * 4] = hi;
        *(uint2*)&Blo[rr * SA + c16 * 4] = lo;
    }
    if (tid < 128) {
        int G = (tid & 3) * 64 + 32 * half + (tid >> 2);
        bsum[tid] = bih[G] + bhh[G];
    }

    const int qrow = lane >> 2;
    const int qk = (lane & 3) * 2;

    int ti = blockIdx.x;
    {
        const float* Xt = X + (size_t)ti * 128 * K;
        for (int i = tid; i < 128 * K / 4; i += 256)
            cp_async16(stage + i * 4, Xt + i * 4);
        asm volatile("cp.async.commit_group;" ::: "memory");
    }

    for (; ti < ntiles; ti += gridDim.x) {
        asm volatile("cp.async.wait_group 0;" ::: "memory");
        __syncthreads();
        for (int i = tid; i < 128 * K / 4; i += 256) {
            int row = i / (K / 4), c4 = (i % (K / 4)) * 4;
            float4 v = *(float4*)&stage[i * 4];
            uint2 hi, lo;
            split4(v, hi, lo);
            *(uint2*)&Ahi[row * SA + c4] = hi;
            *(uint2*)&Alo[row * SA + c4] = lo;
        }
        __syncthreads();
        if (ti + (int)gridDim.x < ntiles) {
            const float* Xt = X + (size_t)(ti + gridDim.x) * 128 * K;
            for (int i = tid; i < 128 * K / 4; i += 256)
                cp_async16(stage + i * 4, Xt + i * 4);
            asm volatile("cp.async.commit_group;" ::: "memory");
        }

        float c[2][8][4];
#pragma unroll
        for (int i = 0; i < 2; i++)
#pragma unroll
            for (int j = 0; j < 8; j++)
#pragma unroll
                for (int q = 0; q < 4; q++) c[i][j][q] = 0.0f;

#pragma unroll
        for (int kc = 0; kc < K / 16; kc++) {
            uint32_t Bh[4][4], Bl[4][4];
#pragma unroll
            for (int jp = 0; jp < 4; jp++) {
                int base = (wn * 64 + jp * 16 + qrow) * SA + kc * 16 + qk;
                Bh[jp][0] = *(const uint32_t*)&Bhi[base];
                Bh[jp][1] = *(const uint32_t*)&Bhi[base + 8];
                Bh[jp][2] = *(const uint32_t*)&Bhi[base + 8 * SA];
                Bh[jp][3] = *(const uint32_t*)&Bhi[base + 8 * SA + 8];
                Bl[jp][0] = *(const uint32_t*)&Blo[base];
                Bl[jp][1] = *(const uint32_t*)&Blo[base + 8];
                Bl[jp][2] = *(const uint32_t*)&Blo[base + 8 * SA];
                Bl[jp][3] = *(const uint32_t*)&Blo[base + 8 * SA + 8];
            }
#pragma unroll
            for (int ib = 0; ib < 2; ib++) {
                int base = (wm * 32 + ib * 16 + qrow) * SA + kc * 16 + qk;
                uint32_t Ah[4], Al[4];
                Ah[0] = *(const uint32_t*)&Ahi[base];
                Ah[1] = *(const uint32_t*)&Ahi[base + 8 * SA];
                Ah[2] = *(const uint32_t*)&Ahi[base + 8];
                Ah[3] = *(const uint32_t*)&Ahi[base + 8 * SA + 8];
                Al[0] = *(const uint32_t*)&Alo[base];
                Al[1] = *(const uint32_t*)&Alo[base + 8 * SA];
                Al[2] = *(const uint32_t*)&Alo[base + 8];
                Al[3] = *(const uint32_t*)&Alo[base + 8 * SA + 8];
#pragma unroll
                for (int jp = 0; jp < 4; jp++)
#pragma unroll
                    for (int h = 0; h < 2; h++) {
                        float* cc = c[ib][jp * 2 + h];
                        mma_bf16(cc, Ah, &Bh[jp][h * 2]);
                        mma_bf16(cc, Ah, &Bl[jp][h * 2]);
                        mma_bf16(cc, Al, &Bh[jp][h * 2]);
                    }
            }
        }

        const size_t token0 = (size_t)ti * 128;
#pragma unroll
        for (int ib = 0; ib < 2; ib++) {
            size_t row = token0 + wm * 32 + ib * 16 + qrow;
#pragma unroll
            for (int j = 0; j < 8; j++) {
                int col = wn * 64 + j * 8 + qk;
                float b0 = bsum[col], b1 = bsum[col + 1];
                *(float2*)&gxo[row * 256 + col] =
                    make_float2(c[ib][j][0] + b0, c[ib][j][1] + b1);
                *(float2*)&gxo[(row + 8) * 256 + col] =
                    make_float2(c[ib][j][2] + b0, c[ib][j][3] + b1);
            }
        }
        __syncthreads();
    }
}

// ---------------- mma recurrence: gates_t = gx_t + h @ Whh'^T ----------------
// Paired h layout (LDS.64 fragment loads), MUFU.TANH activations, running
// pointers, unroll-2 role swap, split accumulators (MT=1).
template <bool VERT, int T, int STOT, int NSEQ, int OT, int SDIV, int OHI>
__global__ void __launch_bounds__(256, 1)
lstm_recur_mma(const float* __restrict__ WhhF, const float* __restrict__ WhhB) {
    constexpr int MT = NSEQ / 16;
    constexpr bool SACC = (MT == 1);
    constexpr int SWW = 72;    // weight staging stride (bf16)
    constexpr int SW = 80;     // h-state stride (bf16): 40 words = 8 mod 32 -> LDS.64 conflict-free
    constexpr int NG = MT * 4;
    extern __shared__ char smraw[];
    uint16_t* WHi = (uint16_t*)smraw;            // weight staging (transient)
    uint16_t* WLo = WHi + 256 * SWW;
    uint16_t* hHi0 = (uint16_t*)smraw;           // h double buffers (alias staging)
    uint16_t* hLo0 = hHi0 + NSEQ * SW;
    uint16_t* hHi1 = hLo0 + NSEQ * SW;
    uint16_t* hLo1 = hHi1 + NSEQ * SW;

    const int tid = threadIdx.x;
    const int wn = tid >> 5;
    const int lane = tid & 31;
    const int qrow = lane >> 2;
    const int qk = (lane & 3) * 2;
    const int par = lane & 1;
    const int dir = blockIdx.y;
    const int s0 = blockIdx.x * NSEQ;

    const float* Whh = dir ? WhhB : WhhF;
    const float* gxd = g_gx + (size_t)dir * ((size_t)262144 * 256);
    float* outbuf = VERT ? g_vout : g_vbuf;

    // stage permuted Whh hi/lo
    for (int i = tid; i < 256 * 16; i += 256) {
        int rr = i >> 4, c16 = i & 15;
        int src = (rr & 3) * 64 + (rr >> 2);
        float4 v = ((const float4*)Whh)[src * 16 + c16];
        uint2 hi, lo;
        split4(v, hi, lo);
        *(uint2*)&WHi[rr * SWW + c16 * 4] = hi;
        *(uint2*)&WLo[rr * SWW + c16 * 4] = lo;
    }
    __syncthreads();

    uint32_t Bh[2][4][4], Bl[2][4][4];
#pragma unroll
    for (int jp = 0; jp < 2; jp++)
#pragma unroll
        for (int kc = 0; kc < 4; kc++) {
            int base = (wn * 32 + jp * 16 + qrow) * SWW + kc * 16 + qk;
            Bh[jp][kc][0] = *(const uint32_t*)&WHi[base];
            Bh[jp][kc][1] = *(const uint32_t*)&WHi[base + 8];
            Bh[jp][kc][2] = *(const uint32_t*)&WHi[base + 8 * SWW];
            Bh[jp][kc][3] = *(const uint32_t*)&WHi[base + 8 * SWW + 8];
            Bl[jp][kc][0] = *(const uint32_t*)&WLo[base];
            Bl[jp][kc][1] = *(const uint32_t*)&WLo[base + 8];
            Bl[jp][kc][2] = *(const uint32_t*)&WLo[base + 8 * SWW];
            Bl[jp][kc][3] = *(const uint32_t*)&WLo[base + 8 * SWW + 8];
        }
    __syncthreads();   // done reading staging; alias as h buffers

    for (int i = tid; i < NSEQ * SW; i += 256) { hHi0[i] = 0; hLo0[i] = 0; }

    // running pointers + precomputed per-group offsets
    const int tt0 = dir ? (T - 1) : 0;
    const int dstep = dir ? -(STOT * 256) : (STOT * 256);
    const float* gp = gxd + ((size_t)tt0 * STOT + s0 + qrow) * 256 + wn * 32 + qk;
    const int dOT = dir ? -OT : OT;
    float* op = outbuf + (size_t)tt0 * OT + (size_t)dir * 64;
    int ooff[NG], hwoff[NG];
#pragma unroll
    for (int mt = 0; mt < MT; mt++)
#pragma unroll
        for (int jp = 0; jp < 2; jp++)
#pragma unroll
            for (int h8 = 0; h8 < 2; h8++) {
                int g = mt * 4 + jp * 2 + h8;
                int j = wn * 8 + jp * 4 + h8 * 2 + (qk >> 2);
                int myrow = mt * 16 + qrow + par * 8;
                int s = s0 + myrow;
                ooff[g] = (s / SDIV) * OHI + (s % SDIV) * 128 + j;
                // paired layout position of hidden unit j:
                int j16 = j & 15, blk = j >> 4;
                int m = j16 >> 1, odd = j16 & 1;
                int sl = (m < 4) ? (m << 1) : (((m - 4) << 1) + 1);
                hwoff[g] = myrow * SW + blk * 16 + sl * 2 + odd;
            }
    const int abase = qrow * SW + (lane & 3) * 4;   // u16 idx; per kc add kc*16

    float cur[MT][2][2][4], nxt[MT][2][2][4];
#pragma unroll
    for (int mt = 0; mt < MT; mt++)
#pragma unroll
        for (int jp = 0; jp < 2; jp++)
#pragma unroll
            for (int h8 = 0; h8 < 2; h8++) {
                const float* p = gp + mt * (16 * 256) + jp * 16 + h8 * 8;
                float2 ab = *(const float2*)p;
                float2 cd = *(const float2*)(p + 8 * 256);
                cur[mt][jp][h8][0] = ab.x; cur[mt][jp][h8][1] = ab.y;
                cur[mt][jp][h8][2] = cd.x; cur[mt][jp][h8][3] = cd.y;
            }
    gp += dstep;

    float creg[MT][2][2];
#pragma unroll
    for (int mt = 0; mt < MT; mt++)
#pragma unroll
        for (int jp = 0; jp < 2; jp++)
#pragma unroll
            for (int h8 = 0; h8 < 2; h8++) creg[mt][jp][h8] = 0.0f;
    __syncthreads();

#define LSTM_STEP(RHI, RLO, WHI_, WLO_, CUR, NXT, TQ)                            \
    do {                                                                         \
        if ((TQ) + 1 < T) {                                                      \
            _Pragma("unroll") for (int mt = 0; mt < MT; mt++)                    \
            _Pragma("unroll") for (int jp = 0; jp < 2; jp++)                     \
            _Pragma("unroll") for (int h8 = 0; h8 < 2; h8++) {                   \
                const float* p = gp + mt * (16 * 256) + jp * 16 + h8 * 8;        \
                float2 ab = *(const float2*)p;                                   \
                float2 cd = *(const float2*)(p + 8 * 256);                       \
                NXT[mt][jp][h8][0] = ab.x; NXT[mt][jp][h8][1] = ab.y;            \
                NXT[mt][jp][h8][2] = cd.x; NXT[mt][jp][h8][3] = cd.y;            \
            }                                                                    \
        }                                                                        \
        float accB[MT][2][2][4];                                                 \
        if (SACC) {                                                              \
            _Pragma("unroll") for (int mt = 0; mt < MT; mt++)                    \
            _Pragma("unroll") for (int jp = 0; jp < 2; jp++)                     \
            _Pragma("unroll") for (int h8 = 0; h8 < 2; h8++)                     \
            _Pragma("unroll") for (int q = 0; q < 4; q++)                        \
                accB[mt][jp][h8][q] = 0.0f;                                      \
        }                                                                        \
        _Pragma("unroll") for (int kc = 0; kc < 4; kc++) {                       \
            uint32_t Ah[MT][4], Al[MT][4];                                       \
            _Pragma("unroll") for (int mt = 0; mt < MT; mt++) {                  \
                int base = abase + mt * 16 * SW + kc * 16;                       \
                uint2 v0 = *(const uint2*)&RHI[base];                            \
                uint2 v1 = *(const uint2*)&RHI[base + 8 * SW];                   \
                Ah[mt][0] = v0.x; Ah[mt][2] = v0.y;                              \
                Ah[mt][1] = v1.x; Ah[mt][3] = v1.y;                              \
                uint2 w0 = *(const uint2*)&RLO[base];                            \
                uint2 w1 = *(const uint2*)&RLO[base + 8 * SW];                   \
                Al[mt][0] = w0.x; Al[mt][2] = w0.y;                              \
                Al[mt][1] = w1.x; Al[mt][3] = w1.y;                              \
            }                                                                    \
            _Pragma("unroll") for (int mt = 0; mt < MT; mt++)                    \
            _Pragma("unroll") for (int jp = 0; jp < 2; jp++)                     \
            _Pragma("unroll") for (int h8 = 0; h8 < 2; h8++) {                   \
                mma_bf16(CUR[mt][jp][h8], Ah[mt], &Bh[jp][kc][h8 * 2]);          \
                float* tb = SACC ? accB[mt][jp][h8] : CUR[mt][jp][h8];           \
                mma_bf16(tb, Ah[mt], &Bl[jp][kc][h8 * 2]);                       \
                mma_bf16(tb, Al[mt], &Bh[jp][kc][h8 * 2]);                       \
            }                                                                    \
        }                                                                        \
        _Pragma("unroll") for (int mt = 0; mt < MT; mt++)                        \
        _Pragma("unroll") for (int jp = 0; jp < 2; jp++)                         \
        _Pragma("unroll") for (int h8 = 0; h8 < 2; h8++) {                       \
            int g = mt * 4 + jp * 2 + h8;                                        \
            float cc0 = CUR[mt][jp][h8][0], cc1 = CUR[mt][jp][h8][1];            \
            float cc2 = CUR[mt][jp][h8][2], cc3 = CUR[mt][jp][h8][3];            \
            if (SACC) {                                                          \
                cc0 += accB[mt][jp][h8][0]; cc1 += accB[mt][jp][h8][1];          \
                cc2 += accB[mt][jp][h8][2]; cc3 += accB[mt][jp][h8][3];          \
            }                                                                    \
            float s0v = par ? cc0 : cc2;                                         \
            float s1v = par ? cc1 : cc3;                                         \
            float r0 = __shfl_xor_sync(0xFFFFFFFFu, s0v, 1);                     \
            float r1 = __shfl_xor_sync(0xFFFFFFFFu, s1v, 1);                     \
            float iv, fv, gv, ov;                                                \
            if (!par) { iv = cc0; fv = cc1; gv = r0; ov = r1; }                  \
            else      { iv = r0;  fv = r1;  gv = cc2; ov = cc3; }                \
            float si = fmaf(0.5f, tanh_ap(0.5f * iv), 0.5f);                     \
            float sf = fmaf(0.5f, tanh_ap(0.5f * fv), 0.5f);                     \
            float so = fmaf(0.5f, tanh_ap(0.5f * ov), 0.5f);                     \
            float tg = tanh_ap(gv);                                              \
            float cst = sf * creg[mt][jp][h8] + si * tg;                         \
            creg[mt][jp][h8] = cst;                                              \
            float hv = so * tanh_ap(cst);                                        \
            uint16_t hb, lb;                                                     \
            split1(hv, hb, lb);                                                  \
            WHI_[hwoff[g]] = hb;                                                 \
            WLO_[hwoff[g]] = lb;                                                 \
            op[ooff[g]] = hv;                                                    \
        }                                                                        \
        gp += dstep;                                                             \
        op += dOT;                                                               \
        __syncthreads();                                                         \
    } while (0)

    for (int t = 0; t < T; t += 2) {
        LSTM_STEP(hHi0, hLo0, hHi1, hLo1, cur, nxt, t);
        LSTM_STEP(hHi1, hLo1, hHi0, hLo0, nxt, cur, t + 1);
    }
#undef LSTM_STEP
}

// ---------------- launch ----------------
extern "C" void kernel_launch(void* const* d_in, const int* in_sizes, int n_in,
                              void* d_out, int out_size) {
    const float* img    = (const float*)d_in[0];
    const float* hWihF  = (const float*)d_in[1];
    const float* hWhhF  = (const float*)d_in[2];
    const float* hbihF  = (const float*)d_in[3];
    const float* hbhhF  = (const float*)d_in[4];
    const float* hWihB  = (const float*)d_in[5];
    const float* hWhhB  = (const float*)d_in[6];
    const float* hbihB  = (const float*)d_in[7];
    const float* hbhhB  = (const float*)d_in[8];
    const float* vWihF  = (const float*)d_in[9];
    const float* vWhhF  = (const float*)d_in[10];
    const float* vbihF  = (const float*)d_in[11];
    const float* vbhhF  = (const float*)d_in[12];
    const float* vWihB  = (const float*)d_in[13];
    const float* vWhhB  = (const float*)d_in[14];
    const float* vbihB  = (const float*)d_in[15];
    const float* vbhhB  = (const float*)d_in[16];
    float* out = (float*)d_out;

    auto hG = gx_gemm<64, false>;
    auto vG = gx_gemm<128, true>;
    auto hR = lstm_recur_mma<false, 256, 1024, 16, 1024, 8, 262144>;
    auto vR = lstm_recur_mma<true, 128, 2048, 32, 262144, (1 << 28), 0>;

    const int smemHG = 128 * 64 * 4 + 4 * 128 * (64 + 8) * 2 + 512;    // 107,008 B
    const int smemVG = 128 * 128 * 4 + 4 * 128 * (128 + 8) * 2 + 512;  // 205,312 B
    // recurrence smem: max(weight staging 2*256*72*2, h buffers 4*NSEQ*80*2)
    const int smemR = 2 * 256 * 72 * 2;                                //  73,728 B
    cudaFuncSetAttribute(hG, cudaFuncAttributeMaxDynamicSharedMemorySize, smemHG);
    cudaFuncSetAttribute(vG, cudaFuncAttributeMaxDynamicSharedMemorySize, smemVG);
    cudaFuncSetAttribute(hR, cudaFuncAttributeMaxDynamicSharedMemorySize, smemR);
    cudaFuncSetAttribute(vR, cudaFuncAttributeMaxDynamicSharedMemorySize, smemR);

    // 1) img -> g_xh
    transpose_in_k<<<dim3(WW / 32, DD / 32, HH * BB), dim3(32, 8)>>>(img);

    // 2) gxh (permuted, bias folded)
    hG<<<dim3(37, 4), 256, smemHG>>>(hWihF, hWihB, hbihF, hbhhF, hbihB, hbhhB, 2048);

    // 3) capture-alignment probe (keeps hR at launch #4 for ncu)
    probe_k<<<1, 32>>>();

    // 4) horizontal mma recurrence -> g_vbuf
    hR<<<dim3(64, 2), 256, smemR>>>(hWhhF, hWhhB);

    // 5) gxv
    vG<<<dim3(37, 4), 256, smemVG>>>(vWihF, vWihB, vbihF, vbhhF, vbihB, vbhhB, 2048);

    // 6) vertical mma recurrence -> g_vout
    vR<<<dim3(64, 2), 256, smemR>>>(vWhhF, vWhhB);

    // 7) g_vout -> out
    transpose_out_k<<<dim3(WW / 32, 128 / 32, HH * BB), dim3(32, 8)>>>(out);
}

// round 15
// speedup vs baseline: 2.4532x; 1.0429x over previous
#include <cuda_runtime.h>
#include <cuda_bf16.h>
#include <math.h>
#include <stdint.h>

#define BB 8
#define DD 64
#define HH 128
#define WW 256

// ---------------- scratch (static device globals) ----------------
// ONLY referenced from device code (host-side symbol use = host shadow under ATS!)
__device__ float g_xh[(size_t)WW * HH * BB * DD];       // [w][h*8+b][64]
__device__ float g_vbuf[(size_t)HH * WW * BB * 128];    // [h][w*8+b][128]
__device__ float g_vout[(size_t)HH * WW * BB * 128];    // [h][w*8+b][128]
__device__ float g_gx[(size_t)2 * 262144 * 256];        // [dir][token][perm gate 4j+g], bias folded

__device__ __forceinline__ uint32_t smem_u32(const void* p) {
    uint32_t a;
    asm("{ .reg .u64 t; cvta.to.shared.u64 t, %1; cvt.u32.u64 %0, t; }" : "=r"(a) : "l"(p));
    return a;
}

__device__ __forceinline__ void cp_async16(void* dst, const void* src) {
    asm volatile("cp.async.cg.shared.global [%0], [%1], 16;"
                 :: "r"(smem_u32(dst)), "l"(src) : "memory");
}

__device__ __forceinline__ void mma_bf16(float* c, const uint32_t* a, const uint32_t* b) {
    asm volatile(
        "mma.sync.aligned.m16n8k16.row.col.f32.bf16.bf16.f32 "
        "{%0,%1,%2,%3}, {%4,%5,%6,%7}, {%8,%9}, {%0,%1,%2,%3};"
        : "+f"(c[0]), "+f"(c[1]), "+f"(c[2]), "+f"(c[3])
        : "r"(a[0]), "r"(a[1]), "r"(a[2]), "r"(a[3]), "r"(b[0]), "r"(b[1]));
}

__device__ __forceinline__ float tanh_ap(float x) {
    float y;
    asm("tanh.approx.f32 %0, %1;" : "=f"(y) : "f"(x));
    return y;
}

__device__ __forceinline__ uint32_t pack_bf16x2(float a, float b) {
    uint32_t r;
    asm("{ .reg .b16 lo, hi;\n\t"
        "cvt.rn.bf16.f32 lo, %1;\n\t"
        "cvt.rn.bf16.f32 hi, %2;\n\t"
        "mov.b32 %0, {lo, hi}; }"
        : "=r"(r) : "f"(a), "f"(b));
    return r;
}

// hi = truncated-bf16 (integer bit ops), lo = rn-bf16 of exact residual
__device__ __forceinline__ void split4(float4 v, uint2& hi, uint2& lo) {
    uint32_t ux = __float_as_uint(v.x), uy = __float_as_uint(v.y);
    uint32_t uz = __float_as_uint(v.z), uw = __float_as_uint(v.w);
    hi.x = (ux >> 16) | (uy & 0xFFFF0000u);
    hi.y = (uz >> 16) | (uw & 0xFFFF0000u);
    float lx = v.x - __uint_as_float(ux & 0xFFFF0000u);
    float ly = v.y - __uint_as_float(uy & 0xFFFF0000u);
    float lz = v.z - __uint_as_float(uz & 0xFFFF0000u);
    float lw = v.w - __uint_as_float(uw & 0xFFFF0000u);
    lo.x = pack_bf16x2(lx, ly);
    lo.y = pack_bf16x2(lz, lw);
}

__device__ __forceinline__ void split1(float x, uint16_t& h, uint16_t& l) {
    uint32_t u = __float_as_uint(x);
    h = (uint16_t)(u >> 16);
    float r = x - __uint_as_float(u & 0xFFFF0000u);
    uint16_t lb;
    asm("cvt.rn.bf16.f32 %0, %1;" : "=h"(lb) : "f"(r));
    l = lb;
}

// capture-alignment probe: keeps ncu -c 1 on the hR launch (#4). Does nothing.
__global__ void probe_k() {}

// ---------------- transposes ----------------
__global__ void transpose_in_k(const float* __restrict__ img) {
    __shared__ float tile[32][33];
    const int tx = threadIdx.x, ty = threadIdx.y;
    const int b = blockIdx.z & 7, h = blockIdx.z >> 3;
    const int w0 = blockIdx.x * 32, d0 = blockIdx.y * 32;
#pragma unroll
    for (int i = 0; i < 32; i += 8) {
        int d = d0 + ty + i;
        tile[ty + i][tx] = img[(((size_t)b * DD + d) * HH + h) * WW + w0 + tx];
    }
    __syncthreads();
#pragma unroll
    for (int i = 0; i < 32; i += 8) {
        int w = w0 + ty + i;
        g_xh[((size_t)w * (HH * BB) + blockIdx.z) * DD + d0 + tx] = tile[tx][ty + i];
    }
}

__global__ void transpose_out_k(float* __restrict__ out) {
    __shared__ float tile[32][33];
    const int tx = threadIdx.x, ty = threadIdx.y;
    const int b = blockIdx.z & 7, h = blockIdx.z >> 3;
    const int w0 = blockIdx.x * 32, c0 = blockIdx.y * 32;
#pragma unroll
    for (int i = 0; i < 32; i += 8) {
        int w = w0 + ty + i;
        tile[ty + i][tx] =
            g_vout[(size_t)h * (WW * BB * 128) + ((size_t)w * BB + b) * 128 + c0 + tx];
    }
    __syncthreads();
#pragma unroll
    for (int i = 0; i < 32; i += 8) {
        int c = c0 + ty + i;
        out[(((size_t)b * 128 + c) * HH + h) * WW + w0 + tx] = tile[tx][ty + i];
    }
}

// ---------------- gx GEMM: gx[dir][token][perm 4j+g] = X @ Wih^T + bias ----------------
template <int K, bool VERT>
__global__ void __launch_bounds__(256, 1)
gx_gemm(const float* __restrict__ WF, const float* __restrict__ WB,
        const float* __restrict__ bihF, const float* __restrict__ bhhF,
        const float* __restrict__ bihB, const float* __restrict__ bhhB, int ntiles) {
    constexpr int SA = K + 8;
    extern __shared__ float smf[];
    float* stage = smf;                               // 128*K fp32
    uint16_t* Ahi = (uint16_t*)(stage + 128 * K);     // 128*SA each
    uint16_t* Alo = Ahi + 128 * SA;
    uint16_t* Bhi = Alo + 128 * SA;
    uint16_t* Blo = Bhi + 128 * SA;
    float* bsum = (float*)(Blo + 128 * SA);           // 128

    const float* X = VERT ? g_vbuf : g_xh;

    const int tid = threadIdx.x;
    const int warp = tid >> 5;
    const int lane = tid & 31;
    const int wm = warp & 3;
    const int wn = warp >> 2;
    const int half = blockIdx.y & 1;
    const int dir = blockIdx.y >> 1;

    const float* W = dir ? WB : WF;
    const float* bih = dir ? bihB : bihF;
    const float* bhh = dir ? bhhB : bhhF;
    float* gxo = g_gx + (size_t)dir * ((size_t)262144 * 256) + half * 128;

    for (int i = tid; i < 128 * (K / 4); i += 256) {
        int rr = i / (K / 4), c16 = i % (K / 4);
        int src = (rr & 3) * 64 + 32 * half + (rr >> 2);
        float4 v = ((const float4*)W)[src * (K / 4) + c16];
        uint2 hi, lo;
        split4(v, hi, lo);
        *(uint2*)&Bhi[rr * SA + c16 * 4] = hi;
        *(uint2*)&Blo[rr * SA + c16 * 4] = lo;
    }
    if (tid < 128) {
        int G = (tid & 3) * 64 + 32 * half + (tid >> 2);
        bsum[tid] = bih[G] + bhh[G];
    }

    const int qrow = lane >> 2;
    const int qk = (lane & 3) * 2;

    int ti = blockIdx.x;
    {
        const float* Xt = X + (size_t)ti * 128 * K;
        for (int i = tid; i < 128 * K / 4; i += 256)
            cp_async16(stage + i * 4, Xt + i * 4);
        asm volatile("cp.async.commit_group;" ::: "memory");
    }

    for (; ti < ntiles; ti += gridDim.x) {
        asm volatile("cp.async.wait_group 0;" ::: "memory");
        __syncthreads();
        for (int i = tid; i < 128 * K / 4; i += 256) {
            int row = i / (K / 4), c4 = (i % (K / 4)) * 4;
            float4 v = *(float4*)&stage[i * 4];
            uint2 hi, lo;
            split4(v, hi, lo);
            *(uint2*)&Ahi[row * SA + c4] = hi;
            *(uint2*)&Alo[row * SA + c4] = lo;
        }
        __syncthreads();
        if (ti + (int)gridDim.x < ntiles) {
            const float* Xt = X + (size_t)(ti + gridDim.x) * 128 * K;
            for (int i = tid; i < 128 * K / 4; i += 256)
                cp_async16(stage + i * 4, Xt + i * 4);
            asm volatile("cp.async.commit_group;" ::: "memory");
        }

        float c[2][8][4];
#pragma unroll
        for (int i = 0; i < 2; i++)
#pragma unroll
            for (int j = 0; j < 8; j++)
#pragma unroll
                for (int q = 0; q < 4; q++) c[i][j][q] = 0.0f;

#pragma unroll
        for (int kc = 0; kc < K / 16; kc++) {
            uint32_t Bh[4][4], Bl[4][4];
#pragma unroll
            for (int jp = 0; jp < 4; jp++) {
                int base = (wn * 64 + jp * 16 + qrow) * SA + kc * 16 + qk;
                Bh[jp][0] = *(const uint32_t*)&Bhi[base];
                Bh[jp][1] = *(const uint32_t*)&Bhi[base + 8];
                Bh[jp][2] = *(const uint32_t*)&Bhi[base + 8 * SA];
                Bh[jp][3] = *(const uint32_t*)&Bhi[base + 8 * SA + 8];
                Bl[jp][0] = *(const uint32_t*)&Blo[base];
                Bl[jp][1] = *(const uint32_t*)&Blo[base + 8];
                Bl[jp][2] = *(const uint32_t*)&Blo[base + 8 * SA];
                Bl[jp][3] = *(const uint32_t*)&Blo[base + 8 * SA + 8];
            }
#pragma unroll
            for (int ib = 0; ib < 2; ib++) {
                int base = (wm * 32 + ib * 16 + qrow) * SA + kc * 16 + qk;
                uint32_t Ah[4], Al[4];
                Ah[0] = *(const uint32_t*)&Ahi[base];
                Ah[1] = *(const uint32_t*)&Ahi[base + 8 * SA];
                Ah[2] = *(const uint32_t*)&Ahi[base + 8];
                Ah[3] = *(const uint32_t*)&Ahi[base + 8 * SA + 8];
                Al[0] = *(const uint32_t*)&Alo[base];
                Al[1] = *(const uint32_t*)&Alo[base + 8 * SA];
                Al[2] = *(const uint32_t*)&Alo[base + 8];
                Al[3] = *(const uint32_t*)&Alo[base + 8 * SA + 8];
#pragma unroll
                for (int jp = 0; jp < 4; jp++)
#pragma unroll
                    for (int h = 0; h < 2; h++) {
                        float* cc = c[ib][jp * 2 + h];
                        mma_bf16(cc, Ah, &Bh[jp][h * 2]);
                        mma_bf16(cc, Ah, &Bl[jp][h * 2]);
                        mma_bf16(cc, Al, &Bh[jp][h * 2]);
                    }
            }
        }

        const size_t token0 = (size_t)ti * 128;
#pragma unroll
        for (int ib = 0; ib < 2; ib++) {
            size_t row = token0 + wm * 32 + ib * 16 + qrow;
#pragma unroll
            for (int j = 0; j < 8; j++) {
                int col = wn * 64 + j * 8 + qk;
                float b0 = bsum[col], b1 = bsum[col + 1];
                *(float2*)&gxo[row * 256 + col] =
                    make_float2(c[ib][j][0] + b0, c[ib][j][1] + b1);
                *(float2*)&gxo[(row + 8) * 256 + col] =
                    make_float2(c[ib][j][2] + b0, c[ib][j][3] + b1);
            }
        }
        __syncthreads();
    }
}

// ---------------- mma recurrence: gates_t = gx_t + h @ Whh'^T ----------------
// 512 threads / 16 warps; each warp owns 16 perm-cols. Paired h layout
// (LDS.64 fragment loads), MUFU.TANH, running pointers, unroll-2 role swap,
// 3-way split accumulator chains when MT==1 (depth 4 instead of 8).
template <bool VERT, int T, int STOT, int NSEQ, int OT, int SDIV, int OHI>
__global__ void __launch_bounds__(512, 1)
lstm_recur_mma(const float* __restrict__ WhhF, const float* __restrict__ WhhB) {
    constexpr int MT = NSEQ / 16;
    constexpr bool SACC = (MT == 1);
    constexpr int SWW = 72;    // weight staging stride (bf16)
    constexpr int SW = 80;     // h-state stride (bf16)
    constexpr int NG = MT * 2;
    extern __shared__ char smraw[];
    uint16_t* WHi = (uint16_t*)smraw;            // weight staging (transient)
    uint16_t* WLo = WHi + 256 * SWW;
    uint16_t* hHi0 = (uint16_t*)smraw;           // h double buffers (alias staging)
    uint16_t* hLo0 = hHi0 + NSEQ * SW;
    uint16_t* hHi1 = hLo0 + NSEQ * SW;
    uint16_t* hLo1 = hHi1 + NSEQ * SW;

    const int tid = threadIdx.x;
    const int wn = tid >> 5;            // 0..15, warp owns perm cols [wn*16, wn*16+16)
    const int lane = tid & 31;
    const int qrow = lane >> 2;
    const int qk = (lane & 3) * 2;
    const int par = lane & 1;
    const int dir = blockIdx.y;
    const int s0 = blockIdx.x * NSEQ;

    const float* Whh = dir ? WhhB : WhhF;
    const float* gxd = g_gx + (size_t)dir * ((size_t)262144 * 256);
    float* outbuf = VERT ? g_vout : g_vbuf;

    // stage permuted Whh hi/lo
    for (int i = tid; i < 256 * 16; i += 512) {
        int rr = i >> 4, c16 = i & 15;
        int src = (rr & 3) * 64 + (rr >> 2);
        float4 v = ((const float4*)Whh)[src * 16 + c16];
        uint2 hi, lo;
        split4(v, hi, lo);
        *(uint2*)&WHi[rr * SWW + c16 * 4] = hi;
        *(uint2*)&WLo[rr * SWW + c16 * 4] = lo;
    }
    __syncthreads();

    uint32_t Bh[4][4], Bl[4][4];        // [kc][reg] for this warp's 16 cols
#pragma unroll
    for (int kc = 0; kc < 4; kc++) {
        int base = (wn * 16 + qrow) * SWW + kc * 16 + qk;
        Bh[kc][0] = *(const uint32_t*)&WHi[base];
        Bh[kc][1] = *(const uint32_t*)&WHi[base + 8];
        Bh[kc][2] = *(const uint32_t*)&WHi[base + 8 * SWW];
        Bh[kc][3] = *(const uint32_t*)&WHi[base + 8 * SWW + 8];
        Bl[kc][0] = *(const uint32_t*)&WLo[base];
        Bl[kc][1] = *(const uint32_t*)&WLo[base + 8];
        Bl[kc][2] = *(const uint32_t*)&WLo[base + 8 * SWW];
        Bl[kc][3] = *(const uint32_t*)&WLo[base + 8 * SWW + 8];
    }
    __syncthreads();   // done reading staging; alias as h buffers

    for (int i = tid; i < NSEQ * SW; i += 512) { hHi0[i] = 0; hLo0[i] = 0; }

    // running pointers + precomputed per-group offsets
    const int tt0 = dir ? (T - 1) : 0;
    const int dstep = dir ? -(STOT * 256) : (STOT * 256);
    const float* gp = gxd + ((size_t)tt0 * STOT + s0 + qrow) * 256 + wn * 16 + qk;
    const int dOT = dir ? -OT : OT;
    float* op = outbuf + (size_t)tt0 * OT + (size_t)dir * 64;
    int ooff[NG], hwoff[NG];
#pragma unroll
    for (int mt = 0; mt < MT; mt++)
#pragma unroll
        for (int h8 = 0; h8 < 2; h8++) {
            int g = mt * 2 + h8;
            int j = wn * 4 + h8 * 2 + (qk >> 2);
            int myrow = mt * 16 + qrow + par * 8;
            int s = s0 + myrow;
            ooff[g] = (s / SDIV) * OHI + (s % SDIV) * 128 + j;
            // paired layout position of hidden unit j:
            int j16 = j & 15, blk = j >> 4;
            int m = j16 >> 1, odd = j16 & 1;
            int sl = (m < 4) ? (m << 1) : (((m - 4) << 1) + 1);
            hwoff[g] = myrow * SW + blk * 16 + sl * 2 + odd;
        }
    const int abase = qrow * SW + (lane & 3) * 4;   // u16 idx; per kc add kc*16

    float cur[MT][2][4], nxt[MT][2][4];
#pragma unroll
    for (int mt = 0; mt < MT; mt++)
#pragma unroll
        for (int h8 = 0; h8 < 2; h8++) {
            const float* p = gp + mt * (16 * 256) + h8 * 8;
            float2 ab = *(const float2*)p;
            float2 cd = *(const float2*)(p + 8 * 256);
            cur[mt][h8][0] = ab.x; cur[mt][h8][1] = ab.y;
            cur[mt][h8][2] = cd.x; cur[mt][h8][3] = cd.y;
        }
    gp += dstep;

    float creg[MT][2];
#pragma unroll
    for (int mt = 0; mt < MT; mt++)
#pragma unroll
        for (int h8 = 0; h8 < 2; h8++) creg[mt][h8] = 0.0f;
    __syncthreads();

#define LSTM_STEP(RHI, RLO, WHI_, WLO_, CUR, NXT, TQ)                            \
    do {                                                                         \
        if ((TQ) + 1 < T) {                                                      \
            _Pragma("unroll") for (int mt = 0; mt < MT; mt++)                    \
            _Pragma("unroll") for (int h8 = 0; h8 < 2; h8++) {                   \
                const float* p = gp + mt * (16 * 256) + h8 * 8;                  \
                float2 ab = *(const float2*)p;                                   \
                float2 cd = *(const float2*)(p + 8 * 256);                       \
                NXT[mt][h8][0] = ab.x; NXT[mt][h8][1] = ab.y;                    \
                NXT[mt][h8][2] = cd.x; NXT[mt][h8][3] = cd.y;                    \
            }                                                                    \
        }                                                                        \
        float acc1[MT][2][4], acc2[MT][2][4];                                    \
        if (SACC) {                                                              \
            _Pragma("unroll") for (int mt = 0; mt < MT; mt++)                    \
            _Pragma("unroll") for (int h8 = 0; h8 < 2; h8++)                     \
            _Pragma("unroll") for (int q = 0; q < 4; q++) {                      \
                acc1[mt][h8][q] = 0.0f; acc2[mt][h8][q] = 0.0f;                  \
            }                                                                    \
        }                                                                        \
        _Pragma("unroll") for (int kc = 0; kc < 4; kc++) {                       \
            uint32_t Ah[MT][4], Al[MT][4];                                       \
            _Pragma("unroll") for (int mt = 0; mt < MT; mt++) {                  \
                int base = abase + mt * 16 * SW + kc * 16;                       \
                uint2 v0 = *(const uint2*)&RHI[base];                            \
                uint2 v1 = *(const uint2*)&RHI[base + 8 * SW];                   \
                Ah[mt][0] = v0.x; Ah[mt][2] = v0.y;                              \
                Ah[mt][1] = v1.x; Ah[mt][3] = v1.y;                              \
                uint2 w0 = *(const uint2*)&RLO[base];                            \
                uint2 w1 = *(const uint2*)&RLO[base + 8 * SW];                   \
                Al[mt][0] = w0.x; Al[mt][2] = w0.y;                              \
                Al[mt][1] = w1.x; Al[mt][3] = w1.y;                              \
            }                                                                    \
            _Pragma("unroll") for (int mt = 0; mt < MT; mt++)                    \
            _Pragma("unroll") for (int h8 = 0; h8 < 2; h8++) {                   \
                mma_bf16(CUR[mt][h8], Ah[mt], &Bh[kc][h8 * 2]);                  \
                float* t1 = SACC ? acc1[mt][h8] : CUR[mt][h8];                   \
                float* t2 = SACC ? acc2[mt][h8] : CUR[mt][h8];                   \
                mma_bf16(t1, Ah[mt], &Bl[kc][h8 * 2]);                           \
                mma_bf16(t2, Al[mt], &Bh[kc][h8 * 2]);                           \
            }                                                                    \
        }                                                                        \
        _Pragma("unroll") for (int mt = 0; mt < MT; mt++)                        \
        _Pragma("unroll") for (int h8 = 0; h8 < 2; h8++) {                       \
            int g = mt * 2 + h8;                                                 \
            float cc0 = CUR[mt][h8][0], cc1 = CUR[mt][h8][1];                    \
            float cc2 = CUR[mt][h8][2], cc3 = CUR[mt][h8][3];                    \
            if (SACC) {                                                          \
                cc0 += acc1[mt][h8][0] + acc2[mt][h8][0];                        \
                cc1 += acc1[mt][h8][1] + acc2[mt][h8][1];                        \
                cc2 += acc1[mt][h8][2] + acc2[mt][h8][2];                        \
                cc3 += acc1[mt][h8][3] + acc2[mt][h8][3];                        \
            }                                                                    \
            float s0v = par ? cc0 : cc2;                                         \
            float s1v = par ? cc1 : cc3;                                         \
            float r0 = __shfl_xor_sync(0xFFFFFFFFu, s0v, 1);                     \
            float r1 = __shfl_xor_sync(0xFFFFFFFFu, s1v, 1);                     \
            float iv, fv, gv, ov;                                                \
            if (!par) { iv = cc0; fv = cc1; gv = r0; ov = r1; }                  \
            else      { iv = r0;  fv = r1;  gv = cc2; ov = cc3; }                \
            float si = fmaf(0.5f, tanh_ap(0.5f * iv), 0.5f);                     \
            float sf = fmaf(0.5f, tanh_ap(0.5f * fv), 0.5f);                     \
            float so = fmaf(0.5f, tanh_ap(0.5f * ov), 0.5f);                     \
            float tg = tanh_ap(gv);                                              \
            float cst = sf * creg[mt][h8] + si * tg;                             \
            creg[mt][h8] = cst;                                                  \
            float hv = so * tanh_ap(cst);                                        \
            uint16_t hb, lb;                                                     \
            split1(hv, hb, lb);                                                  \
            WHI_[hwoff[g]] = hb;                                                 \
            WLO_[hwoff[g]] = lb;                                                 \
            op[ooff[g]] = hv;                                                    \
        }                                                                        \
        gp += dstep;                                                             \
        op += dOT;                                                               \
        __syncthreads();                                                         \
    } while (0)

    for (int t = 0; t < T; t += 2) {
        LSTM_STEP(hHi0, hLo0, hHi1, hLo1, cur, nxt, t);
        LSTM_STEP(hHi1, hLo1, hHi0, hLo0, nxt, cur, t + 1);
    }
#undef LSTM_STEP
}

// ---------------- launch ----------------
extern "C" void kernel_launch(void* const* d_in, const int* in_sizes, int n_in,
                              void* d_out, int out_size) {
    const float* img    = (const float*)d_in[0];
    const float* hWihF  = (const float*)d_in[1];
    const float* hWhhF  = (const float*)d_in[2];
    const float* hbihF  = (const float*)d_in[3];
    const float* hbhhF  = (const float*)d_in[4];
    const float* hWihB  = (const float*)d_in[5];
    const float* hWhhB  = (const float*)d_in[6];
    const float* hbihB  = (const float*)d_in[7];
    const float* hbhhB  = (const float*)d_in[8];
    const float* vWihF  = (const float*)d_in[9];
    const float* vWhhF  = (const float*)d_in[10];
    const float* vbihF  = (const float*)d_in[11];
    const float* vbhhF  = (const float*)d_in[12];
    const float* vWihB  = (const float*)d_in[13];
    const float* vWhhB  = (const float*)d_in[14];
    const float* vbihB  = (const float*)d_in[15];
    const float* vbhhB  = (const float*)d_in[16];
    float* out = (float*)d_out;

    auto hG = gx_gemm<64, false>;
    auto vG = gx_gemm<128, true>;
    auto hR = lstm_recur_mma<false, 256, 1024, 16, 1024, 8, 262144>;
    auto vR = lstm_recur_mma<true, 128, 2048, 32, 262144, (1 << 28), 0>;

    const int smemHG = 128 * 64 * 4 + 4 * 128 * (64 + 8) * 2 + 512;    // 107,008 B
    const int smemVG = 128 * 128 * 4 + 4 * 128 * (128 + 8) * 2 + 512;  // 205,312 B
    // recurrence smem: max(weight staging 2*256*72*2, h buffers 4*NSEQ*80*2)
    const int smemR = 2 * 256 * 72 * 2;                                //  73,728 B
    cudaFuncSetAttribute(hG, cudaFuncAttributeMaxDynamicSharedMemorySize, smemHG);
    cudaFuncSetAttribute(vG, cudaFuncAttributeMaxDynamicSharedMemorySize, smemVG);
    cudaFuncSetAttribute(hR, cudaFuncAttributeMaxDynamicSharedMemorySize, smemR);
    cudaFuncSetAttribute(vR, cudaFuncAttributeMaxDynamicSharedMemorySize, smemR);

    // 1) img -> g_xh
    transpose_in_k<<<dim3(WW / 32, DD / 32, HH * BB), dim3(32, 8)>>>(img);

    // 2) gxh (permuted, bias folded)
    hG<<<dim3(37, 4), 256, smemHG>>>(hWihF, hWihB, hbihF, hbhhF, hbihB, hbhhB, 2048);

    // 3) capture-alignment probe (keeps hR at launch #4 for ncu)
    probe_k<<<1, 32>>>();

    // 4) horizontal mma recurrence -> g_vbuf (512 threads / 16 warps)
    hR<<<dim3(64, 2), 512, smemR>>>(hWhhF, hWhhB);

    // 5) gxv
    vG<<<dim3(37, 4), 256, smemVG>>>(vWihF, vWihB, vbihF, vbhhF, vbihB, vbhhB, 2048);

    // 6) vertical mma recurrence -> g_vout (512 threads / 16 warps)
    vR<<<dim3(64, 2), 512, smemR>>>(vWhhF, vWhhB);

    // 7) g_vout -> out
    transpose_out_k<<<dim3(WW / 32, 128 / 32, HH * BB), dim3(32, 8)>>>(out);
}